// round 2
// baseline (speedup 1.0000x reference)
#include <cuda_runtime.h>

#define D 64
#define MAXN 100000
#define MAXE 1600000
#define BN_EPS 1e-5f
#define NSLOT 32

// ---------------- scratch (static __device__, allocation-free) ----------------
static __device__ float g_acc[(size_t)MAXN * D];              // (1+eps)*h + scatter-sum
static __device__ float g_hn[(size_t)MAXN * D];               // MLP(node) pre-norm
static __device__ float g_en[(size_t)MAXE * D];               // MLP(edge) pre-norm
static __device__ float g_partial[2 * NSLOT * 2 * D];         // [path][slot][sum|sumsq][col]
static __device__ float g_final[4 * D];                       // [path][scale|shift][col]

// ---------------- K0: init accumulator + zero stat partials ----------------
__global__ void k_init(const float* __restrict__ h, const float* __restrict__ eps,
                       int n_nodes) {
    int i = blockIdx.x * blockDim.x + threadIdx.x;
    int total4 = n_nodes * (D / 4);
    if (i < total4) {
        float s = 1.0f + __ldg(eps);
        float4 v = *((const float4*)h + i);
        v.x *= s; v.y *= s; v.z *= s; v.w *= s;
        *((float4*)g_acc + i) = v;
    }
    if (i < 2 * NSLOT * 2 * D) g_partial[i] = 0.0f;
}

// ---------------- K1: scatter-add h[src] onto acc[dst] ----------------
__global__ void k_scatter(const float* __restrict__ h, const int* __restrict__ src,
                          const int* __restrict__ dst, int n_edges) {
    long long t = (long long)blockIdx.x * blockDim.x + threadIdx.x;
    int e = (int)(t >> 4);
    if (e >= n_edges) return;
    int part = ((int)t & 15) * 4;
    int s = __ldg(src + e);
    int d = __ldg(dst + e);
    const float4 v = *(const float4*)(h + (size_t)s * D + part);
    float* p = g_acc + (size_t)d * D + part;
    atomicAdd(p + 0, v.x);
    atomicAdd(p + 1, v.y);
    atomicAdd(p + 2, v.z);
    atomicAdd(p + 3, v.w);
}

// ---------------- K2/K3: fused 2-layer MLP over a 64-row tile + BN stats ----------------
// src_sel: 0 -> X = g_acc (nodes), 1 -> X = Xext (edges)
// path:    0 -> Y = g_hn, partial slot group 0; 1 -> Y = g_en, group 1
__global__ __launch_bounds__(256, 4)
void k_mlp(const float* __restrict__ Xext,
           const float* __restrict__ W1, const float* __restrict__ b1,
           const float* __restrict__ W2, const float* __restrict__ b2,
           int src_sel, int path, int nrows) {
    __shared__ float Xs[D][68];   // input tile (row-major), later reused for Y
    __shared__ float Ws[D][68];   // weight tile (W1 then W2)
    __shared__ float Hs[D][68];   // hidden (relu) tile

    const float* X = (src_sel == 0) ? g_acc : Xext;
    float* Y = (path == 0) ? g_hn : g_en;

    int tid = threadIdx.x;
    int tx = tid & 15, ty = tid >> 4;
    int r0 = ty * 4, c0 = tx * 4;
    int base = blockIdx.x * 64;
    int valid = nrows - base;
    if (valid > 64) valid = 64;

    // load X tile (zero-pad invalid rows)
#pragma unroll
    for (int i = 0; i < 4; i++) {
        int lin = tid + i * 256;       // 0..1023 covers 64 rows x 16 float4
        int row = lin >> 4;
        int c4 = (lin & 15) * 4;
        float4 v = make_float4(0.f, 0.f, 0.f, 0.f);
        if (row < valid) v = *(const float4*)(X + (size_t)(base + row) * D + c4);
        *(float4*)&Xs[row][c4] = v;
    }
    // load W1
#pragma unroll
    for (int i = 0; i < 4; i++) {
        int lin = tid + i * 256;
        int k = lin >> 4;
        int c4 = (lin & 15) * 4;
        *(float4*)&Ws[k][c4] = *(const float4*)(W1 + k * D + c4);
    }
    __syncthreads();

    // layer 1: H = relu(X @ W1 + b1)
    float acc[4][4];
#pragma unroll
    for (int j = 0; j < 4; j++) {
        float bv = __ldg(b1 + c0 + j);
        acc[0][j] = bv; acc[1][j] = bv; acc[2][j] = bv; acc[3][j] = bv;
    }
#pragma unroll 8
    for (int k = 0; k < D; k++) {
        float a0 = Xs[r0 + 0][k], a1 = Xs[r0 + 1][k], a2 = Xs[r0 + 2][k], a3 = Xs[r0 + 3][k];
        float4 w = *(const float4*)&Ws[k][c0];
        acc[0][0] += a0 * w.x; acc[0][1] += a0 * w.y; acc[0][2] += a0 * w.z; acc[0][3] += a0 * w.w;
        acc[1][0] += a1 * w.x; acc[1][1] += a1 * w.y; acc[1][2] += a1 * w.z; acc[1][3] += a1 * w.w;
        acc[2][0] += a2 * w.x; acc[2][1] += a2 * w.y; acc[2][2] += a2 * w.z; acc[2][3] += a2 * w.w;
        acc[3][0] += a3 * w.x; acc[3][1] += a3 * w.y; acc[3][2] += a3 * w.z; acc[3][3] += a3 * w.w;
    }
#pragma unroll
    for (int i = 0; i < 4; i++) {
        float4 hv;
        hv.x = fmaxf(acc[i][0], 0.f); hv.y = fmaxf(acc[i][1], 0.f);
        hv.z = fmaxf(acc[i][2], 0.f); hv.w = fmaxf(acc[i][3], 0.f);
        *(float4*)&Hs[r0 + i][c0] = hv;
    }
    __syncthreads();

    // load W2 (overwrite Ws)
#pragma unroll
    for (int i = 0; i < 4; i++) {
        int lin = tid + i * 256;
        int k = lin >> 4;
        int c4 = (lin & 15) * 4;
        *(float4*)&Ws[k][c4] = *(const float4*)(W2 + k * D + c4);
    }
    __syncthreads();

    // layer 2: Y = H @ W2 + b2
#pragma unroll
    for (int j = 0; j < 4; j++) {
        float bv = __ldg(b2 + c0 + j);
        acc[0][j] = bv; acc[1][j] = bv; acc[2][j] = bv; acc[3][j] = bv;
    }
#pragma unroll 8
    for (int k = 0; k < D; k++) {
        float a0 = Hs[r0 + 0][k], a1 = Hs[r0 + 1][k], a2 = Hs[r0 + 2][k], a3 = Hs[r0 + 3][k];
        float4 w = *(const float4*)&Ws[k][c0];
        acc[0][0] += a0 * w.x; acc[0][1] += a0 * w.y; acc[0][2] += a0 * w.z; acc[0][3] += a0 * w.w;
        acc[1][0] += a1 * w.x; acc[1][1] += a1 * w.y; acc[1][2] += a1 * w.z; acc[1][3] += a1 * w.w;
        acc[2][0] += a2 * w.x; acc[2][1] += a2 * w.y; acc[2][2] += a2 * w.z; acc[2][3] += a2 * w.w;
        acc[3][0] += a3 * w.x; acc[3][1] += a3 * w.y; acc[3][2] += a3 * w.z; acc[3][3] += a3 * w.w;
    }

    // write Y to global + stash Y tile in Xs (Xs fully consumed before the last barrier)
#pragma unroll
    for (int i = 0; i < 4; i++) {
        int row = base + r0 + i;
        float4 yv = make_float4(acc[i][0], acc[i][1], acc[i][2], acc[i][3]);
        if (row < nrows) *(float4*)(Y + (size_t)row * D + c0) = yv;
        *(float4*)&Xs[r0 + i][c0] = yv;
    }
    __syncthreads();

    // BN stats: per-column sum & sumsq over valid rows -> slotted global atomics
    if (tid < D) {
        int col = tid;
        float s = 0.f, q = 0.f;
        for (int r = 0; r < valid; r++) {
            float v = Xs[r][col];
            s += v;
            q += v * v;
        }
        int slot = blockIdx.x & (NSLOT - 1);
        float* p = g_partial + ((path * NSLOT + slot) * 2) * D;
        atomicAdd(p + col, s);
        atomicAdd(p + D + col, q);
    }
}

// ---------------- K4: finalize BN -> per-column scale/shift ----------------
__global__ void k_finalize(const float* __restrict__ gamma_h, const float* __restrict__ beta_h,
                           const float* __restrict__ gamma_e, const float* __restrict__ beta_e,
                           int n_nodes, int n_edges) {
    int t = threadIdx.x;            // 128 threads
    int path = t >> 6;
    int col = t & 63;
    float n = (path == 0) ? (float)n_nodes : (float)n_edges;
    float s = 0.f, q = 0.f;
    for (int slot = 0; slot < NSLOT; slot++) {
        const float* p = g_partial + ((path * NSLOT + slot) * 2) * D;
        s += p[col];
        q += p[D + col];
    }
    float mean = s / n;
    float var = q / n - mean * mean;
    float rstd = rsqrtf(var + BN_EPS);
    float gamma = (path == 0) ? __ldg(gamma_h + col) : __ldg(gamma_e + col);
    float beta  = (path == 0) ? __ldg(beta_h + col)  : __ldg(beta_e + col);
    float scale = gamma * rstd;
    float shift = beta - mean * scale;
    g_final[path * 2 * D + col] = scale;
    g_final[path * 2 * D + D + col] = shift;
}

// ---------------- K5/K6: epilogue  out = in + relu(scale*y + shift) ----------------
__global__ void k_epi(const float* __restrict__ inp, int path,
                      float* __restrict__ out, int nrows) {
    int i = blockIdx.x * blockDim.x + threadIdx.x;
    int total4 = nrows * (D / 4);
    if (i >= total4) return;
    const float* y = (path == 0) ? g_hn : g_en;
    int c4 = (i & 15) * 4;
    const float* sc = g_final + path * 2 * D;
    const float* sh = sc + D;
    float4 yv = *((const float4*)y + i);
    float4 xv = *((const float4*)inp + i);
    float4 o;
    o.x = xv.x + fmaxf(fmaf(sc[c4 + 0], yv.x, sh[c4 + 0]), 0.f);
    o.y = xv.y + fmaxf(fmaf(sc[c4 + 1], yv.y, sh[c4 + 1]), 0.f);
    o.z = xv.z + fmaxf(fmaf(sc[c4 + 2], yv.z, sh[c4 + 2]), 0.f);
    o.w = xv.w + fmaxf(fmaf(sc[c4 + 3], yv.w, sh[c4 + 3]), 0.f);
    *((float4*)out + i) = o;
}

// ---------------- launch ----------------
extern "C" void kernel_launch(void* const* d_in, const int* in_sizes, int n_in,
                              void* d_out, int out_size) {
    const float* h   = (const float*)d_in[0];
    const float* e   = (const float*)d_in[1];
    const int*   src = (const int*)d_in[2];
    const int*   dst = (const int*)d_in[3];
    const float* eps = (const float*)d_in[4];
    const float* W1  = (const float*)d_in[5];
    const float* b1  = (const float*)d_in[6];
    const float* W2  = (const float*)d_in[7];
    const float* b2  = (const float*)d_in[8];
    const float* gh  = (const float*)d_in[9];
    const float* bh  = (const float*)d_in[10];
    const float* ge  = (const float*)d_in[11];
    const float* be  = (const float*)d_in[12];

    int n_nodes = in_sizes[0] / D;
    int n_edges = in_sizes[1] / D;
    float* out = (float*)d_out;
    float* out_h = out;
    float* out_e = out + (size_t)n_nodes * D;

    int t4n = n_nodes * (D / 4);                 // node float4 count
    int t4e = n_edges * (D / 4);

    // K0: init acc + zero partials
    k_init<<<(t4n + 255) / 256, 256>>>(h, eps, n_nodes);
    // K1: scatter-add
    {
        long long threads = (long long)n_edges * 16;
        int blocks = (int)((threads + 255) / 256);
        k_scatter<<<blocks, 256>>>(h, src, dst, n_edges);
    }
    // K2: node MLP + stats
    k_mlp<<<(n_nodes + 63) / 64, 256>>>(nullptr, W1, b1, W2, b2, /*src_sel=*/0, /*path=*/0, n_nodes);
    // K3: edge MLP + stats
    k_mlp<<<(n_edges + 63) / 64, 256>>>(e, W1, b1, W2, b2, /*src_sel=*/1, /*path=*/1, n_edges);
    // K4: finalize BN
    k_finalize<<<1, 128>>>(gh, bh, ge, be, n_nodes, n_edges);
    // K5: node epilogue
    k_epi<<<(t4n + 255) / 256, 256>>>(h, /*path=*/0, out_h, n_nodes);
    // K6: edge epilogue
    k_epi<<<(t4e + 255) / 256, 256>>>(e, /*path=*/1, out_e, n_edges);
}

// round 6
// speedup vs baseline: 1.4801x; 1.4801x over previous
#include <cuda_runtime.h>
#include <cuda_bf16.h>

#define D 64
#define MAXN 100000
#define MAXE 1600000
#define BN_EPS 1e-5f
#define NSLOT 32

#define TROWS 256          // rows per MLP block
#define XSTR 72            // padded bf16 row stride (144B) -> conflict-free ldmatrix
#define WSTR 72

// ---------------- scratch (static __device__, allocation-free) ----------------
static __device__ float g_acc[(size_t)MAXN * D];              // (1+eps)*h + scatter-sum
static __device__ float g_hn[(size_t)MAXN * D];               // MLP(node) pre-norm
static __device__ float g_en[(size_t)MAXE * D];               // MLP(edge) pre-norm
static __device__ float g_partial[2 * NSLOT * 2 * D];         // [path][slot][sum|sumsq][col]
static __device__ float g_final[4 * D];                       // [path][scale|shift][col]

// ---------------- K0: init accumulator + zero stat partials ----------------
__global__ void k_init(const float* __restrict__ h, const float* __restrict__ eps,
                       int n_nodes) {
    int i = blockIdx.x * blockDim.x + threadIdx.x;
    int total4 = n_nodes * (D / 4);
    if (i < total4) {
        float s = 1.0f + __ldg(eps);
        float4 v = *((const float4*)h + i);
        v.x *= s; v.y *= s; v.z *= s; v.w *= s;
        *((float4*)g_acc + i) = v;
    }
    if (i < 2 * NSLOT * 2 * D) g_partial[i] = 0.0f;
}

// ---------------- K1: scatter-add h[src] onto acc[dst] ----------------
__global__ void k_scatter(const float* __restrict__ h, const int* __restrict__ src,
                          const int* __restrict__ dst, int n_edges) {
    long long t = (long long)blockIdx.x * blockDim.x + threadIdx.x;
    int e = (int)(t >> 4);
    if (e >= n_edges) return;
    int part = ((int)t & 15) * 4;
    int s = __ldg(src + e);
    int d = __ldg(dst + e);
    const float4 v = *(const float4*)(h + (size_t)s * D + part);
    float* p = g_acc + (size_t)d * D + part;
    atomicAdd(p + 0, v.x);
    atomicAdd(p + 1, v.y);
    atomicAdd(p + 2, v.z);
    atomicAdd(p + 3, v.w);
}

// ---------------- tensor-core MLP helpers ----------------
__device__ __forceinline__ void ldmA(unsigned* a, const __nv_bfloat16* p) {
    unsigned addr = (unsigned)__cvta_generic_to_shared(p);
    asm volatile("ldmatrix.sync.aligned.m8n8.x4.shared.b16 {%0,%1,%2,%3}, [%4];"
                 : "=r"(a[0]), "=r"(a[1]), "=r"(a[2]), "=r"(a[3]) : "r"(addr));
}
__device__ __forceinline__ void ldmB(unsigned* b, const __nv_bfloat16* p) {
    unsigned addr = (unsigned)__cvta_generic_to_shared(p);
    asm volatile("ldmatrix.sync.aligned.m8n8.x2.trans.shared.b16 {%0,%1}, [%2];"
                 : "=r"(b[0]), "=r"(b[1]) : "r"(addr));
}
__device__ __forceinline__ void mma_bf16(float* c, const unsigned* a, const unsigned* b) {
    asm volatile("mma.sync.aligned.m16n8k16.row.col.f32.bf16.bf16.f32 "
                 "{%0,%1,%2,%3}, {%4,%5,%6,%7}, {%8,%9}, {%0,%1,%2,%3};"
                 : "+f"(c[0]), "+f"(c[1]), "+f"(c[2]), "+f"(c[3])
                 : "r"(a[0]), "r"(a[1]), "r"(a[2]), "r"(a[3]), "r"(b[0]), "r"(b[1]));
}
__device__ __forceinline__ void split2(float x, __nv_bfloat16& hi, __nv_bfloat16& lo) {
    hi = __float2bfloat16_rn(x);
    lo = __float2bfloat16_rn(x - __bfloat162float(hi));
}

__device__ __forceinline__ void load_w_split(const float* __restrict__ W,
                                             __nv_bfloat16* Wh, __nv_bfloat16* Wl, int tid) {
#pragma unroll
    for (int i = 0; i < 4; i++) {
        int lin = tid + i * 256;          // 1024 float4 = 64 x 16
        int k = lin >> 4;
        int c4 = (lin & 15) << 2;
        float4 v = *(const float4*)(W + k * D + c4);
        __nv_bfloat16 h0, l0, h1, l1, h2, l2, h3, l3;
        split2(v.x, h0, l0); split2(v.y, h1, l1); split2(v.z, h2, l2); split2(v.w, h3, l3);
        __nv_bfloat162* ph = (__nv_bfloat162*)(Wh + k * WSTR + c4);
        __nv_bfloat162* pl = (__nv_bfloat162*)(Wl + k * WSTR + c4);
        ph[0] = __nv_bfloat162(h0, h1); ph[1] = __nv_bfloat162(h2, h3);
        pl[0] = __nv_bfloat162(l0, l1); pl[1] = __nv_bfloat162(l2, l3);
    }
}

// one 64x64 layer for this warp's 32 rows: acc = X(rows) @ W + bias
__device__ __forceinline__ void do_layer(const __nv_bfloat16* Xh, const __nv_bfloat16* Xl,
                                         const __nv_bfloat16* Wh, const __nv_bfloat16* Wl,
                                         const float* __restrict__ bias,
                                         float acc[2][8][4], int warp, int lane) {
    int qp = lane & 3;
#pragma unroll
    for (int nt = 0; nt < 8; nt++) {
        float bv0 = __ldg(bias + nt * 8 + 2 * qp);
        float bv1 = __ldg(bias + nt * 8 + 2 * qp + 1);
#pragma unroll
        for (int mt = 0; mt < 2; mt++) {
            acc[mt][nt][0] = bv0; acc[mt][nt][1] = bv1;
            acc[mt][nt][2] = bv0; acc[mt][nt][3] = bv1;
        }
    }
    int rowbase = warp * 32;
    int arow = lane & 15;
    int akoff = (lane >> 4) * 8;
    int bk = lane & 15;
#pragma unroll
    for (int kk = 0; kk < 4; kk++) {
        unsigned a1[2][4], a2[2][4];
#pragma unroll
        for (int mt = 0; mt < 2; mt++) {
            ldmA(a1[mt], Xh + (rowbase + mt * 16 + arow) * XSTR + kk * 16 + akoff);
            ldmA(a2[mt], Xl + (rowbase + mt * 16 + arow) * XSTR + kk * 16 + akoff);
        }
#pragma unroll
        for (int nt = 0; nt < 8; nt++) {
            unsigned b1r[2], b2r[2];
            ldmB(b1r, Wh + (kk * 16 + bk) * WSTR + nt * 8);
            ldmB(b2r, Wl + (kk * 16 + bk) * WSTR + nt * 8);
#pragma unroll
            for (int mt = 0; mt < 2; mt++) {
                mma_bf16(acc[mt][nt], a1[mt], b1r);   // x_hi * w_hi
                mma_bf16(acc[mt][nt], a1[mt], b2r);   // x_hi * w_lo
                mma_bf16(acc[mt][nt], a2[mt], b1r);   // x_lo * w_hi
            }
        }
    }
}

// ---------------- K2/K3: tensor-core fused 2-layer MLP + BN stats ----------------
__global__ __launch_bounds__(256, 2)
void k_mlp_tc(const float* __restrict__ Xext,
              const float* __restrict__ W1, const float* __restrict__ b1,
              const float* __restrict__ W2, const float* __restrict__ b2,
              int src_sel, int path, int nrows) {
    extern __shared__ char smem_raw[];
    __nv_bfloat16* Xh = (__nv_bfloat16*)smem_raw;
    __nv_bfloat16* Xl = Xh + TROWS * XSTR;
    __nv_bfloat16* Wh = Xl + TROWS * XSTR;
    __nv_bfloat16* Wl = Wh + D * WSTR;
    float* sstat = (float*)(Wl + D * WSTR);    // [sum(64) | sumsq(64)]

    const float* X = (src_sel == 0) ? g_acc : Xext;
    float* Y = (path == 0) ? g_hn : g_en;

    int tid = threadIdx.x;
    int warp = tid >> 5;
    int lane = tid & 31;
    int g = lane >> 2;
    int qp = lane & 3;
    int base = blockIdx.x * TROWS;
    int valid = nrows - base; if (valid > TROWS) valid = TROWS;

    if (tid < 2 * D) sstat[tid] = 0.f;

    // load X tile, split into bf16 hi/lo (zero-pad invalid rows)
#pragma unroll
    for (int i = 0; i < 16; i++) {
        int lin = tid + i * 256;          // 4096 float4 = 256 rows x 16
        int row = lin >> 4;
        int c4 = (lin & 15) << 2;
        float4 v = make_float4(0.f, 0.f, 0.f, 0.f);
        if (row < valid) v = *(const float4*)(X + (size_t)(base + row) * D + c4);
        __nv_bfloat16 h0, l0, h1, l1, h2, l2, h3, l3;
        split2(v.x, h0, l0); split2(v.y, h1, l1); split2(v.z, h2, l2); split2(v.w, h3, l3);
        __nv_bfloat162* ph = (__nv_bfloat162*)(Xh + row * XSTR + c4);
        __nv_bfloat162* pl = (__nv_bfloat162*)(Xl + row * XSTR + c4);
        ph[0] = __nv_bfloat162(h0, h1); ph[1] = __nv_bfloat162(h2, h3);
        pl[0] = __nv_bfloat162(l0, l1); pl[1] = __nv_bfloat162(l2, l3);
    }
    load_w_split(W1, Wh, Wl, tid);
    __syncthreads();

    float acc[2][8][4];
    do_layer(Xh, Xl, Wh, Wl, b1, acc, warp, lane);
    __syncthreads();                      // all reads of X / W1 complete

    // relu + split H back into Xh/Xl (each warp owns its 32 rows)
#pragma unroll
    for (int mt = 0; mt < 2; mt++) {
#pragma unroll
        for (int nt = 0; nt < 8; nt++) {
            int ra = warp * 32 + mt * 16 + g;
            int col = nt * 8 + 2 * qp;
            float v0 = fmaxf(acc[mt][nt][0], 0.f);
            float v1 = fmaxf(acc[mt][nt][1], 0.f);
            float v2 = fmaxf(acc[mt][nt][2], 0.f);
            float v3 = fmaxf(acc[mt][nt][3], 0.f);
            __nv_bfloat16 h0, l0, h1, l1, h2, l2, h3, l3;
            split2(v0, h0, l0); split2(v1, h1, l1);
            split2(v2, h2, l2); split2(v3, h3, l3);
            *(__nv_bfloat162*)(Xh + ra * XSTR + col) = __nv_bfloat162(h0, h1);
            *(__nv_bfloat162*)(Xl + ra * XSTR + col) = __nv_bfloat162(l0, l1);
            *(__nv_bfloat162*)(Xh + (ra + 8) * XSTR + col) = __nv_bfloat162(h2, h3);
            *(__nv_bfloat162*)(Xl + (ra + 8) * XSTR + col) = __nv_bfloat162(l2, l3);
        }
    }
    load_w_split(W2, Wh, Wl, tid);
    __syncthreads();

    do_layer(Xh, Xl, Wh, Wl, b2, acc, warp, lane);

    // write Y + block BN stats
#pragma unroll
    for (int mt = 0; mt < 2; mt++) {
#pragma unroll
        for (int nt = 0; nt < 8; nt++) {
            int ra = base + warp * 32 + mt * 16 + g;
            int rb = ra + 8;
            int col = nt * 8 + 2 * qp;
            float c0 = acc[mt][nt][0], c1 = acc[mt][nt][1];
            float c2 = acc[mt][nt][2], c3 = acc[mt][nt][3];
            bool va = ra < nrows, vb = rb < nrows;
            if (va) *(float2*)(Y + (size_t)ra * D + col) = make_float2(c0, c1);
            if (vb) *(float2*)(Y + (size_t)rb * D + col) = make_float2(c2, c3);
            float s0 = (va ? c0 : 0.f) + (vb ? c2 : 0.f);
            float s1 = (va ? c1 : 0.f) + (vb ? c3 : 0.f);
            float q0 = (va ? c0 * c0 : 0.f) + (vb ? c2 * c2 : 0.f);
            float q1 = (va ? c1 * c1 : 0.f) + (vb ? c3 * c3 : 0.f);
#pragma unroll
            for (int off = 4; off < 32; off <<= 1) {
                s0 += __shfl_xor_sync(0xffffffffu, s0, off);
                s1 += __shfl_xor_sync(0xffffffffu, s1, off);
                q0 += __shfl_xor_sync(0xffffffffu, q0, off);
                q1 += __shfl_xor_sync(0xffffffffu, q1, off);
            }
            if (lane < 4) {               // lane == qp group representative
                atomicAdd(sstat + col, s0);
                atomicAdd(sstat + col + 1, s1);
                atomicAdd(sstat + 64 + col, q0);
                atomicAdd(sstat + 64 + col + 1, q1);
            }
        }
    }
    __syncthreads();
    if (tid < D) {
        int slot = blockIdx.x & (NSLOT - 1);
        float* p = g_partial + ((path * NSLOT + slot) * 2) * D;
        atomicAdd(p + tid, sstat[tid]);
        atomicAdd(p + D + tid, sstat[64 + tid]);
    }
}

// ---------------- K4: finalize BN -> per-column scale/shift ----------------
__global__ void k_finalize(const float* __restrict__ gamma_h, const float* __restrict__ beta_h,
                           const float* __restrict__ gamma_e, const float* __restrict__ beta_e,
                           int n_nodes, int n_edges) {
    int t = threadIdx.x;            // 128 threads
    int path = t >> 6;
    int col = t & 63;
    float n = (path == 0) ? (float)n_nodes : (float)n_edges;
    float s = 0.f, q = 0.f;
    for (int slot = 0; slot < NSLOT; slot++) {
        const float* p = g_partial + ((path * NSLOT + slot) * 2) * D;
        s += p[col];
        q += p[D + col];
    }
    float mean = s / n;
    float var = q / n - mean * mean;
    float rstd = rsqrtf(var + BN_EPS);
    float gamma = (path == 0) ? __ldg(gamma_h + col) : __ldg(gamma_e + col);
    float beta  = (path == 0) ? __ldg(beta_h + col)  : __ldg(beta_e + col);
    float scale = gamma * rstd;
    float shift = beta - mean * scale;
    g_final[path * 2 * D + col] = scale;
    g_final[path * 2 * D + D + col] = shift;
}

// ---------------- K5/K6: epilogue  out = in + relu(scale*y + shift) ----------------
__global__ void k_epi(const float* __restrict__ inp, int path,
                      float* __restrict__ out, int nrows) {
    int i = blockIdx.x * blockDim.x + threadIdx.x;
    int total4 = nrows * (D / 4);
    if (i >= total4) return;
    const float* y = (path == 0) ? g_hn : g_en;
    int c4 = (i & 15) * 4;
    const float* sc = g_final + path * 2 * D;
    const float* sh = sc + D;
    float4 yv = *((const float4*)y + i);
    float4 xv = *((const float4*)inp + i);
    float4 o;
    o.x = xv.x + fmaxf(fmaf(sc[c4 + 0], yv.x, sh[c4 + 0]), 0.f);
    o.y = xv.y + fmaxf(fmaf(sc[c4 + 1], yv.y, sh[c4 + 1]), 0.f);
    o.z = xv.z + fmaxf(fmaf(sc[c4 + 2], yv.z, sh[c4 + 2]), 0.f);
    o.w = xv.w + fmaxf(fmaf(sc[c4 + 3], yv.w, sh[c4 + 3]), 0.f);
    *((float4*)out + i) = o;
}

// ---------------- launch ----------------
extern "C" void kernel_launch(void* const* d_in, const int* in_sizes, int n_in,
                              void* d_out, int out_size) {
    const float* h   = (const float*)d_in[0];
    const float* e   = (const float*)d_in[1];
    const int*   src = (const int*)d_in[2];
    const int*   dst = (const int*)d_in[3];
    const float* eps = (const float*)d_in[4];
    const float* W1  = (const float*)d_in[5];
    const float* b1  = (const float*)d_in[6];
    const float* W2  = (const float*)d_in[7];
    const float* b2  = (const float*)d_in[8];
    const float* gh  = (const float*)d_in[9];
    const float* bh  = (const float*)d_in[10];
    const float* ge  = (const float*)d_in[11];
    const float* be  = (const float*)d_in[12];

    int n_nodes = in_sizes[0] / D;
    int n_edges = in_sizes[1] / D;
    float* out = (float*)d_out;
    float* out_h = out;
    float* out_e = out + (size_t)n_nodes * D;

    int t4n = n_nodes * (D / 4);
    int t4e = n_edges * (D / 4);

    const int SMEM_BYTES = (2 * TROWS * XSTR + 2 * D * WSTR) * 2 + 2 * D * 4;  // 92672
    cudaFuncSetAttribute(k_mlp_tc, cudaFuncAttributeMaxDynamicSharedMemorySize, SMEM_BYTES);

    // K0: init acc + zero partials
    k_init<<<(t4n + 255) / 256, 256>>>(h, eps, n_nodes);
    // K1: scatter-add
    {
        long long threads = (long long)n_edges * 16;
        int blocks = (int)((threads + 255) / 256);
        k_scatter<<<blocks, 256>>>(h, src, dst, n_edges);
    }
    // K2: node MLP + stats
    k_mlp_tc<<<(n_nodes + TROWS - 1) / TROWS, 256, SMEM_BYTES>>>(
        nullptr, W1, b1, W2, b2, /*src_sel=*/0, /*path=*/0, n_nodes);
    // K3: edge MLP + stats
    k_mlp_tc<<<(n_edges + TROWS - 1) / TROWS, 256, SMEM_BYTES>>>(
        e, W1, b1, W2, b2, /*src_sel=*/1, /*path=*/1, n_edges);
    // K4: finalize BN
    k_finalize<<<1, 128>>>(gh, bh, ge, be, n_nodes, n_edges);
    // K5: node epilogue
    k_epi<<<(t4n + 255) / 256, 256>>>(h, /*path=*/0, out_h, n_nodes);
    // K6: edge epilogue
    k_epi<<<(t4e + 255) / 256, 256>>>(e, /*path=*/1, out_e, n_edges);
}

// round 8
// speedup vs baseline: 1.7690x; 1.1952x over previous
#include <cuda_runtime.h>
#include <cuda_bf16.h>

#define D 64
#define MAXN 100000
#define MAXE 1600000
#define BN_EPS 1e-5f
#define NSLOT 32

#define TROWS 256          // rows per MLP block
#define XSTR 72            // padded bf16 row stride (144B) -> conflict-free ldmatrix
#define WSTR 72

// ---------------- scratch (static __device__, allocation-free) ----------------
static __device__ float g_acc[(size_t)MAXN * D];              // (1+eps)*h + scatter-sum
static __device__ float g_hn[(size_t)MAXN * D];               // MLP(node) pre-norm
static __device__ float g_en[(size_t)MAXE * D];               // MLP(edge) pre-norm
static __device__ float g_partial[2 * NSLOT * 2 * D];         // [path][slot][sum|sumsq][col]
static __device__ float g_final[4 * D];                       // [path][scale|shift][col]

// ---------------- K0: init accumulator + zero NODE stat partials only ----------------
__global__ void k_init(const float* __restrict__ h, const float* __restrict__ eps,
                       int n_nodes) {
    int i = blockIdx.x * blockDim.x + threadIdx.x;
    int total4 = n_nodes * (D / 4);
    if (i < total4) {
        float s = 1.0f + __ldg(eps);
        float4 v = *((const float4*)h + i);
        v.x *= s; v.y *= s; v.z *= s; v.w *= s;
        *((float4*)g_acc + i) = v;
    }
    if (i < NSLOT * 2 * D) g_partial[i] = 0.0f;          // path-0 (node) slots only
}

// ---------------- K0b (side stream): zero EDGE stat partials ----------------
__global__ void k_zero_e() {
    int i = blockIdx.x * blockDim.x + threadIdx.x;
    if (i < NSLOT * 2 * D) g_partial[NSLOT * 2 * D + i] = 0.0f;   // path-1 (edge) slots
}

// ---------------- K1: scatter-add h[src] onto acc[dst] (vector red) ----------------
__global__ void k_scatter(const float* __restrict__ h, const int* __restrict__ src,
                          const int* __restrict__ dst, int n_edges) {
    long long t = (long long)blockIdx.x * blockDim.x + threadIdx.x;
    int e = (int)(t >> 4);
    if (e >= n_edges) return;
    int part = ((int)t & 15) * 4;
    int s = __ldg(src + e);
    int d = __ldg(dst + e);
    const float4 v = *(const float4*)(h + (size_t)s * D + part);
    float* p = g_acc + (size_t)d * D + part;
    asm volatile("red.global.add.v4.f32 [%0], {%1,%2,%3,%4};"
                 :: "l"(p), "f"(v.x), "f"(v.y), "f"(v.z), "f"(v.w) : "memory");
}

// ---------------- tensor-core MLP helpers ----------------
__device__ __forceinline__ void ldmA(unsigned* a, const __nv_bfloat16* p) {
    unsigned addr = (unsigned)__cvta_generic_to_shared(p);
    asm volatile("ldmatrix.sync.aligned.m8n8.x4.shared.b16 {%0,%1,%2,%3}, [%4];"
                 : "=r"(a[0]), "=r"(a[1]), "=r"(a[2]), "=r"(a[3]) : "r"(addr));
}
__device__ __forceinline__ void ldmB(unsigned* b, const __nv_bfloat16* p) {
    unsigned addr = (unsigned)__cvta_generic_to_shared(p);
    asm volatile("ldmatrix.sync.aligned.m8n8.x2.trans.shared.b16 {%0,%1}, [%2];"
                 : "=r"(b[0]), "=r"(b[1]) : "r"(addr));
}
__device__ __forceinline__ void mma_bf16(float* c, const unsigned* a, const unsigned* b) {
    asm volatile("mma.sync.aligned.m16n8k16.row.col.f32.bf16.bf16.f32 "
                 "{%0,%1,%2,%3}, {%4,%5,%6,%7}, {%8,%9}, {%0,%1,%2,%3};"
                 : "+f"(c[0]), "+f"(c[1]), "+f"(c[2]), "+f"(c[3])
                 : "r"(a[0]), "r"(a[1]), "r"(a[2]), "r"(a[3]), "r"(b[0]), "r"(b[1]));
}
__device__ __forceinline__ void split2(float x, __nv_bfloat16& hi, __nv_bfloat16& lo) {
    hi = __float2bfloat16_rn(x);
    lo = __float2bfloat16_rn(x - __bfloat162float(hi));
}

__device__ __forceinline__ void load_w_split(const float* __restrict__ W,
                                             __nv_bfloat16* Wh, __nv_bfloat16* Wl, int tid) {
#pragma unroll
    for (int i = 0; i < 4; i++) {
        int lin = tid + i * 256;          // 1024 float4 = 64 x 16
        int k = lin >> 4;
        int c4 = (lin & 15) << 2;
        float4 v = *(const float4*)(W + k * D + c4);
        __nv_bfloat16 h0, l0, h1, l1, h2, l2, h3, l3;
        split2(v.x, h0, l0); split2(v.y, h1, l1); split2(v.z, h2, l2); split2(v.w, h3, l3);
        __nv_bfloat162* ph = (__nv_bfloat162*)(Wh + k * WSTR + c4);
        __nv_bfloat162* pl = (__nv_bfloat162*)(Wl + k * WSTR + c4);
        ph[0] = __nv_bfloat162(h0, h1); ph[1] = __nv_bfloat162(h2, h3);
        pl[0] = __nv_bfloat162(l0, l1); pl[1] = __nv_bfloat162(l2, l3);
    }
}

// one 64x64 layer for this warp's 32 rows: acc = X(rows) @ W + bias
__device__ __forceinline__ void do_layer(const __nv_bfloat16* Xh, const __nv_bfloat16* Xl,
                                         const __nv_bfloat16* Wh, const __nv_bfloat16* Wl,
                                         const float* __restrict__ bias,
                                         float acc[2][8][4], int warp, int lane) {
    int qp = lane & 3;
#pragma unroll
    for (int nt = 0; nt < 8; nt++) {
        float bv0 = __ldg(bias + nt * 8 + 2 * qp);
        float bv1 = __ldg(bias + nt * 8 + 2 * qp + 1);
#pragma unroll
        for (int mt = 0; mt < 2; mt++) {
            acc[mt][nt][0] = bv0; acc[mt][nt][1] = bv1;
            acc[mt][nt][2] = bv0; acc[mt][nt][3] = bv1;
        }
    }
    int rowbase = warp * 32;
    int arow = lane & 15;
    int akoff = (lane >> 4) * 8;
    int bk = lane & 15;
#pragma unroll
    for (int kk = 0; kk < 4; kk++) {
        unsigned a1[2][4], a2[2][4];
#pragma unroll
        for (int mt = 0; mt < 2; mt++) {
            ldmA(a1[mt], Xh + (rowbase + mt * 16 + arow) * XSTR + kk * 16 + akoff);
            ldmA(a2[mt], Xl + (rowbase + mt * 16 + arow) * XSTR + kk * 16 + akoff);
        }
#pragma unroll
        for (int nt = 0; nt < 8; nt++) {
            unsigned b1r[2], b2r[2];
            ldmB(b1r, Wh + (kk * 16 + bk) * WSTR + nt * 8);
            ldmB(b2r, Wl + (kk * 16 + bk) * WSTR + nt * 8);
#pragma unroll
            for (int mt = 0; mt < 2; mt++) {
                mma_bf16(acc[mt][nt], a1[mt], b1r);   // x_hi * w_hi
                mma_bf16(acc[mt][nt], a1[mt], b2r);   // x_hi * w_lo
                mma_bf16(acc[mt][nt], a2[mt], b1r);   // x_lo * w_hi
            }
        }
    }
}

// ---------------- K2/K3: tensor-core fused 2-layer MLP + BN stats ----------------
__global__ __launch_bounds__(256, 2)
void k_mlp_tc(const float* __restrict__ Xext,
              const float* __restrict__ W1, const float* __restrict__ b1,
              const float* __restrict__ W2, const float* __restrict__ b2,
              int src_sel, int path, int nrows) {
    extern __shared__ char smem_raw[];
    __nv_bfloat16* Xh = (__nv_bfloat16*)smem_raw;
    __nv_bfloat16* Xl = Xh + TROWS * XSTR;
    __nv_bfloat16* Wh = Xl + TROWS * XSTR;
    __nv_bfloat16* Wl = Wh + D * WSTR;
    float* sstat = (float*)(Wl + D * WSTR);    // [sum(64) | sumsq(64)]

    const float* X = (src_sel == 0) ? g_acc : Xext;
    float* Y = (path == 0) ? g_hn : g_en;

    int tid = threadIdx.x;
    int warp = tid >> 5;
    int lane = tid & 31;
    int g = lane >> 2;
    int qp = lane & 3;
    int base = blockIdx.x * TROWS;
    int valid = nrows - base; if (valid > TROWS) valid = TROWS;

    if (tid < 2 * D) sstat[tid] = 0.f;

    // load X tile, split into bf16 hi/lo (zero-pad invalid rows)
#pragma unroll
    for (int i = 0; i < 16; i++) {
        int lin = tid + i * 256;          // 4096 float4 = 256 rows x 16
        int row = lin >> 4;
        int c4 = (lin & 15) << 2;
        float4 v = make_float4(0.f, 0.f, 0.f, 0.f);
        if (row < valid) v = *(const float4*)(X + (size_t)(base + row) * D + c4);
        __nv_bfloat16 h0, l0, h1, l1, h2, l2, h3, l3;
        split2(v.x, h0, l0); split2(v.y, h1, l1); split2(v.z, h2, l2); split2(v.w, h3, l3);
        __nv_bfloat162* ph = (__nv_bfloat162*)(Xh + row * XSTR + c4);
        __nv_bfloat162* pl = (__nv_bfloat162*)(Xl + row * XSTR + c4);
        ph[0] = __nv_bfloat162(h0, h1); ph[1] = __nv_bfloat162(h2, h3);
        pl[0] = __nv_bfloat162(l0, l1); pl[1] = __nv_bfloat162(l2, l3);
    }
    load_w_split(W1, Wh, Wl, tid);
    __syncthreads();

    float acc[2][8][4];
    do_layer(Xh, Xl, Wh, Wl, b1, acc, warp, lane);
    __syncthreads();                      // all reads of X / W1 complete

    // relu + split H back into Xh/Xl (each warp owns its 32 rows)
#pragma unroll
    for (int mt = 0; mt < 2; mt++) {
#pragma unroll
        for (int nt = 0; nt < 8; nt++) {
            int ra = warp * 32 + mt * 16 + g;
            int col = nt * 8 + 2 * qp;
            float v0 = fmaxf(acc[mt][nt][0], 0.f);
            float v1 = fmaxf(acc[mt][nt][1], 0.f);
            float v2 = fmaxf(acc[mt][nt][2], 0.f);
            float v3 = fmaxf(acc[mt][nt][3], 0.f);
            __nv_bfloat16 h0, l0, h1, l1, h2, l2, h3, l3;
            split2(v0, h0, l0); split2(v1, h1, l1);
            split2(v2, h2, l2); split2(v3, h3, l3);
            *(__nv_bfloat162*)(Xh + ra * XSTR + col) = __nv_bfloat162(h0, h1);
            *(__nv_bfloat162*)(Xl + ra * XSTR + col) = __nv_bfloat162(l0, l1);
            *(__nv_bfloat162*)(Xh + (ra + 8) * XSTR + col) = __nv_bfloat162(h2, h3);
            *(__nv_bfloat162*)(Xl + (ra + 8) * XSTR + col) = __nv_bfloat162(l2, l3);
        }
    }
    load_w_split(W2, Wh, Wl, tid);
    __syncthreads();

    do_layer(Xh, Xl, Wh, Wl, b2, acc, warp, lane);

    // write Y + block BN stats
#pragma unroll
    for (int mt = 0; mt < 2; mt++) {
#pragma unroll
        for (int nt = 0; nt < 8; nt++) {
            int ra = base + warp * 32 + mt * 16 + g;
            int rb = ra + 8;
            int col = nt * 8 + 2 * qp;
            float c0 = acc[mt][nt][0], c1 = acc[mt][nt][1];
            float c2 = acc[mt][nt][2], c3 = acc[mt][nt][3];
            bool va = ra < nrows, vb = rb < nrows;
            if (va) *(float2*)(Y + (size_t)ra * D + col) = make_float2(c0, c1);
            if (vb) *(float2*)(Y + (size_t)rb * D + col) = make_float2(c2, c3);
            float s0 = (va ? c0 : 0.f) + (vb ? c2 : 0.f);
            float s1 = (va ? c1 : 0.f) + (vb ? c3 : 0.f);
            float q0 = (va ? c0 * c0 : 0.f) + (vb ? c2 * c2 : 0.f);
            float q1 = (va ? c1 * c1 : 0.f) + (vb ? c3 * c3 : 0.f);
#pragma unroll
            for (int off = 4; off < 32; off <<= 1) {
                s0 += __shfl_xor_sync(0xffffffffu, s0, off);
                s1 += __shfl_xor_sync(0xffffffffu, s1, off);
                q0 += __shfl_xor_sync(0xffffffffu, q0, off);
                q1 += __shfl_xor_sync(0xffffffffu, q1, off);
            }
            if (lane < 4) {               // lane == qp group representative
                atomicAdd(sstat + col, s0);
                atomicAdd(sstat + col + 1, s1);
                atomicAdd(sstat + 64 + col, q0);
                atomicAdd(sstat + 64 + col + 1, q1);
            }
        }
    }
    __syncthreads();
    if (tid < D) {
        int slot = blockIdx.x & (NSLOT - 1);
        float* p = g_partial + ((path * NSLOT + slot) * 2) * D;
        atomicAdd(p + tid, sstat[tid]);
        atomicAdd(p + D + tid, sstat[64 + tid]);
    }
}

// ---------------- K4: finalize BN -> per-column scale/shift ----------------
__global__ void k_finalize(const float* __restrict__ gamma_h, const float* __restrict__ beta_h,
                           const float* __restrict__ gamma_e, const float* __restrict__ beta_e,
                           int n_nodes, int n_edges) {
    int t = threadIdx.x;            // 128 threads
    int path = t >> 6;
    int col = t & 63;
    float n = (path == 0) ? (float)n_nodes : (float)n_edges;
    float s = 0.f, q = 0.f;
    for (int slot = 0; slot < NSLOT; slot++) {
        const float* p = g_partial + ((path * NSLOT + slot) * 2) * D;
        s += p[col];
        q += p[D + col];
    }
    float mean = s / n;
    float var = q / n - mean * mean;
    float rstd = rsqrtf(var + BN_EPS);
    float gamma = (path == 0) ? __ldg(gamma_h + col) : __ldg(gamma_e + col);
    float beta  = (path == 0) ? __ldg(beta_h + col)  : __ldg(beta_e + col);
    float scale = gamma * rstd;
    float shift = beta - mean * scale;
    g_final[path * 2 * D + col] = scale;
    g_final[path * 2 * D + D + col] = shift;
}

// ---------------- K5/K6: epilogue  out = in + relu(scale*y + shift) ----------------
__global__ void k_epi(const float* __restrict__ inp, int path,
                      float* __restrict__ out, int nrows) {
    int i = blockIdx.x * blockDim.x + threadIdx.x;
    int total4 = nrows * (D / 4);
    if (i >= total4) return;
    const float* y = (path == 0) ? g_hn : g_en;
    int c4 = (i & 15) * 4;
    const float* sc = g_final + path * 2 * D;
    const float* sh = sc + D;
    float4 yv = *((const float4*)y + i);
    float4 xv = *((const float4*)inp + i);
    float4 o;
    o.x = xv.x + fmaxf(fmaf(sc[c4 + 0], yv.x, sh[c4 + 0]), 0.f);
    o.y = xv.y + fmaxf(fmaf(sc[c4 + 1], yv.y, sh[c4 + 1]), 0.f);
    o.z = xv.z + fmaxf(fmaf(sc[c4 + 2], yv.z, sh[c4 + 2]), 0.f);
    o.w = xv.w + fmaxf(fmaf(sc[c4 + 3], yv.w, sh[c4 + 3]), 0.f);
    *((float4*)out + i) = o;
}

// ---------------- launch ----------------
static cudaStream_t g_s2 = nullptr;
static cudaEvent_t g_ev0, g_ev1, g_ev2, g_ev3;

extern "C" void kernel_launch(void* const* d_in, const int* in_sizes, int n_in,
                              void* d_out, int out_size) {
    if (g_s2 == nullptr) {   // one-time resource creation (host-side, not captured work)
        cudaStreamCreateWithFlags(&g_s2, cudaStreamNonBlocking);
        cudaEventCreateWithFlags(&g_ev0, cudaEventDisableTiming);
        cudaEventCreateWithFlags(&g_ev1, cudaEventDisableTiming);
        cudaEventCreateWithFlags(&g_ev2, cudaEventDisableTiming);
        cudaEventCreateWithFlags(&g_ev3, cudaEventDisableTiming);
    }

    const float* h   = (const float*)d_in[0];
    const float* e   = (const float*)d_in[1];
    const int*   src = (const int*)d_in[2];
    const int*   dst = (const int*)d_in[3];
    const float* eps = (const float*)d_in[4];
    const float* W1  = (const float*)d_in[5];
    const float* b1  = (const float*)d_in[6];
    const float* W2  = (const float*)d_in[7];
    const float* b2  = (const float*)d_in[8];
    const float* gh  = (const float*)d_in[9];
    const float* bh  = (const float*)d_in[10];
    const float* ge  = (const float*)d_in[11];
    const float* be  = (const float*)d_in[12];

    int n_nodes = in_sizes[0] / D;
    int n_edges = in_sizes[1] / D;
    float* out = (float*)d_out;
    float* out_h = out;
    float* out_e = out + (size_t)n_nodes * D;

    int t4n = n_nodes * (D / 4);
    int t4e = n_edges * (D / 4);

    const int SMEM_BYTES = (2 * TROWS * XSTR + 2 * D * WSTR) * 2 + 2 * D * 4;  // 92672
    cudaFuncSetAttribute(k_mlp_tc, cudaFuncAttributeMaxDynamicSharedMemorySize, SMEM_BYTES);

    // ---- fork: edge chain (zero edge partials -> edge MLP) on side stream ----
    cudaEventRecord(g_ev0, 0);
    cudaStreamWaitEvent(g_s2, g_ev0, 0);
    k_zero_e<<<(NSLOT * 2 * D + 255) / 256, 256, 0, g_s2>>>();
    k_mlp_tc<<<(n_edges + TROWS - 1) / TROWS, 256, SMEM_BYTES, g_s2>>>(
        e, W1, b1, W2, b2, /*src_sel=*/1, /*path=*/1, n_edges);

    // ---- main stream: node chain (init zeroes node partials only) ----
    k_init<<<(t4n + 255) / 256, 256>>>(h, eps, n_nodes);
    {
        long long threads = (long long)n_edges * 16;
        int blocks = (int)((threads + 255) / 256);
        k_scatter<<<blocks, 256>>>(h, src, dst, n_edges);
    }
    k_mlp_tc<<<(n_nodes + TROWS - 1) / TROWS, 256, SMEM_BYTES>>>(
        nullptr, W1, b1, W2, b2, /*src_sel=*/0, /*path=*/0, n_nodes);

    // ---- join: both stat sets complete before finalize ----
    cudaEventRecord(g_ev1, g_s2);
    cudaStreamWaitEvent(0, g_ev1, 0);
    k_finalize<<<1, 128>>>(gh, bh, ge, be, n_nodes, n_edges);

    // ---- fork epilogues: node epi on side stream, edge epi on main ----
    cudaEventRecord(g_ev2, 0);
    cudaStreamWaitEvent(g_s2, g_ev2, 0);
    k_epi<<<(t4n + 255) / 256, 256, 0, g_s2>>>(h, /*path=*/0, out_h, n_nodes);
    k_epi<<<(t4e + 255) / 256, 256>>>(e, /*path=*/1, out_e, n_edges);
    cudaEventRecord(g_ev3, g_s2);
    cudaStreamWaitEvent(0, g_ev3, 0);
}

// round 13
// speedup vs baseline: 1.7879x; 1.0106x over previous
#include <cuda_runtime.h>
#include <cuda_bf16.h>
#include <cuda_fp16.h>

#define D 64
#define MAXN 100000
#define MAXE 1600000
#define BN_EPS 1e-5f
#define NSLOT 32

#define TROWS 256          // rows per MLP block
#define XSTR 72            // padded bf16 row stride (144B) -> conflict-free ldmatrix
#define WSTR 72

// ---------------- scratch (static __device__, allocation-free) ----------------
static __device__ float  g_acc[(size_t)MAXN * D];             // (1+eps)*h + scatter-sum
static __device__ __half g_hn[(size_t)MAXN * D];              // MLP(node) pre-norm (fp16)
static __device__ __half g_en[(size_t)MAXE * D];              // MLP(edge) pre-norm (fp16)
static __device__ float g_partial[2 * NSLOT * 2 * D];         // [path][slot][sum|sumsq][col]
static __device__ float g_final[4 * D];                       // [path][scale|shift][col]

// ---------------- K0: init accumulator + zero NODE stat partials only ----------------
__global__ void k_init(const float* __restrict__ h, const float* __restrict__ eps,
                       int n_nodes) {
    int i = blockIdx.x * blockDim.x + threadIdx.x;
    int total4 = n_nodes * (D / 4);
    if (i < total4) {
        float s = 1.0f + __ldg(eps);
        float4 v = *((const float4*)h + i);
        v.x *= s; v.y *= s; v.z *= s; v.w *= s;
        *((float4*)g_acc + i) = v;
    }
    if (i < NSLOT * 2 * D) g_partial[i] = 0.0f;          // path-0 (node) slots only
}

// ---------------- K0b (side stream): zero EDGE stat partials ----------------
__global__ void k_zero_e() {
    int i = blockIdx.x * blockDim.x + threadIdx.x;
    if (i < NSLOT * 2 * D) g_partial[NSLOT * 2 * D + i] = 0.0f;   // path-1 (edge) slots
}

// ---------------- K1: scatter-add h[src] onto acc[dst] (vector red) ----------------
__global__ void k_scatter(const float* __restrict__ h, const int* __restrict__ src,
                          const int* __restrict__ dst, int n_edges) {
    long long t = (long long)blockIdx.x * blockDim.x + threadIdx.x;
    int e = (int)(t >> 4);
    if (e >= n_edges) return;
    int part = ((int)t & 15) * 4;
    int s = __ldg(src + e);
    int d = __ldg(dst + e);
    const float4 v = *(const float4*)(h + (size_t)s * D + part);
    float* p = g_acc + (size_t)d * D + part;
    asm volatile("red.global.add.v4.f32 [%0], {%1,%2,%3,%4};"
                 :: "l"(p), "f"(v.x), "f"(v.y), "f"(v.z), "f"(v.w) : "memory");
}

// ---------------- tensor-core MLP helpers ----------------
__device__ __forceinline__ void ldmA(unsigned* a, const __nv_bfloat16* p) {
    unsigned addr = (unsigned)__cvta_generic_to_shared(p);
    asm volatile("ldmatrix.sync.aligned.m8n8.x4.shared.b16 {%0,%1,%2,%3}, [%4];"
                 : "=r"(a[0]), "=r"(a[1]), "=r"(a[2]), "=r"(a[3]) : "r"(addr));
}
// x4.trans: loads hi-frag (2 regs) + lo-frag (2 regs) in one instruction.
// Per-lane address supplied by caller (lanes 0-15 -> Wh rows, 16-31 -> Wl rows).
__device__ __forceinline__ void ldmB4(unsigned* b, const __nv_bfloat16* p) {
    unsigned addr = (unsigned)__cvta_generic_to_shared(p);
    asm volatile("ldmatrix.sync.aligned.m8n8.x4.trans.shared.b16 {%0,%1,%2,%3}, [%4];"
                 : "=r"(b[0]), "=r"(b[1]), "=r"(b[2]), "=r"(b[3]) : "r"(addr));
}
__device__ __forceinline__ void mma_bf16(float* c, const unsigned* a, const unsigned* b) {
    asm volatile("mma.sync.aligned.m16n8k16.row.col.f32.bf16.bf16.f32 "
                 "{%0,%1,%2,%3}, {%4,%5,%6,%7}, {%8,%9}, {%0,%1,%2,%3};"
                 : "+f"(c[0]), "+f"(c[1]), "+f"(c[2]), "+f"(c[3])
                 : "r"(a[0]), "r"(a[1]), "r"(a[2]), "r"(a[3]), "r"(b[0]), "r"(b[1]));
}
__device__ __forceinline__ void split2(float x, __nv_bfloat16& hi, __nv_bfloat16& lo) {
    hi = __float2bfloat16_rn(x);
    lo = __float2bfloat16_rn(x - __bfloat162float(hi));
}

__device__ __forceinline__ void load_w_split(const float* __restrict__ W,
                                             __nv_bfloat16* Wh, __nv_bfloat16* Wl, int tid) {
#pragma unroll
    for (int i = 0; i < 4; i++) {
        int lin = tid + i * 256;          // 1024 float4 = 64 x 16
        int k = lin >> 4;
        int c4 = (lin & 15) << 2;
        float4 v = *(const float4*)(W + k * D + c4);
        __nv_bfloat16 h0, l0, h1, l1, h2, l2, h3, l3;
        split2(v.x, h0, l0); split2(v.y, h1, l1); split2(v.z, h2, l2); split2(v.w, h3, l3);
        __nv_bfloat162* ph = (__nv_bfloat162*)(Wh + k * WSTR + c4);
        __nv_bfloat162* pl = (__nv_bfloat162*)(Wl + k * WSTR + c4);
        ph[0] = __nv_bfloat162(h0, h1); ph[1] = __nv_bfloat162(h2, h3);
        pl[0] = __nv_bfloat162(l0, l1); pl[1] = __nv_bfloat162(l2, l3);
    }
}

// one 64x64 layer for this warp's 32 rows: acc = X(rows) @ W + bias
// Wh: hi-split weights; lo-split MUST be at Wh + D*WSTR (contiguous).
__device__ __forceinline__ void do_layer(const __nv_bfloat16* Xh, const __nv_bfloat16* Xl,
                                         const __nv_bfloat16* Wh,
                                         const float* __restrict__ bias,
                                         float acc[2][8][4], int warp, int lane) {
    int qp = lane & 3;
#pragma unroll
    for (int nt = 0; nt < 8; nt++) {
        float bv0 = __ldg(bias + nt * 8 + 2 * qp);
        float bv1 = __ldg(bias + nt * 8 + 2 * qp + 1);
#pragma unroll
        for (int mt = 0; mt < 2; mt++) {
            acc[mt][nt][0] = bv0; acc[mt][nt][1] = bv1;
            acc[mt][nt][2] = bv0; acc[mt][nt][3] = bv1;
        }
    }
    int rowbase = warp * 32;
    int arow = lane & 15;
    int akoff = (lane >> 4) * 8;
    // per-lane B base: lanes 0-15 address Wh rows, lanes 16-31 address Wl rows
    const __nv_bfloat16* wlane = Wh + (lane >> 4) * (D * WSTR) + (lane & 15) * WSTR;
#pragma unroll
    for (int kk = 0; kk < 4; kk++) {
        unsigned a1[2][4], a2[2][4];
#pragma unroll
        for (int mt = 0; mt < 2; mt++) {
            ldmA(a1[mt], Xh + (rowbase + mt * 16 + arow) * XSTR + kk * 16 + akoff);
            ldmA(a2[mt], Xl + (rowbase + mt * 16 + arow) * XSTR + kk * 16 + akoff);
        }
#pragma unroll
        for (int nt = 0; nt < 8; nt++) {
            unsigned b[4];                      // {bh0, bh1, bl0, bl1}
            ldmB4(b, wlane + kk * 16 * WSTR + nt * 8);
#pragma unroll
            for (int mt = 0; mt < 2; mt++) {
                mma_bf16(acc[mt][nt], a1[mt], b + 0);   // x_hi * w_hi
                mma_bf16(acc[mt][nt], a1[mt], b + 2);   // x_hi * w_lo
                mma_bf16(acc[mt][nt], a2[mt], b + 0);   // x_lo * w_hi
            }
        }
    }
}

// ---------------- K2/K3: tensor-core fused 2-layer MLP + BN stats ----------------
__global__ __launch_bounds__(256, 2)
void k_mlp_tc(const float* __restrict__ Xext,
              const float* __restrict__ W1, const float* __restrict__ b1,
              const float* __restrict__ W2, const float* __restrict__ b2,
              int src_sel, int path, int nrows) {
    extern __shared__ char smem_raw[];
    __nv_bfloat16* Xh  = (__nv_bfloat16*)smem_raw;
    __nv_bfloat16* Xl  = Xh  + TROWS * XSTR;
    __nv_bfloat16* W1h = Xl  + TROWS * XSTR;
    __nv_bfloat16* W1l = W1h + D * WSTR;
    __nv_bfloat16* W2h = W1l + D * WSTR;
    __nv_bfloat16* W2l = W2h + D * WSTR;
    float* sstat = (float*)(W2l + D * WSTR);   // [sum(64) | sumsq(64)]

    const float* X = (src_sel == 0) ? g_acc : Xext;
    __half* Y = (path == 0) ? g_hn : g_en;

    int tid = threadIdx.x;
    int warp = tid >> 5;
    int lane = tid & 31;
    int g = lane >> 2;
    int qp = lane & 3;
    int base = blockIdx.x * TROWS;
    int valid = nrows - base; if (valid > TROWS) valid = TROWS;

    if (tid < 2 * D) sstat[tid] = 0.f;

    // load X tile, split into bf16 hi/lo (zero-pad invalid rows)
#pragma unroll
    for (int i = 0; i < 16; i++) {
        int lin = tid + i * 256;          // 4096 float4 = 256 rows x 16
        int row = lin >> 4;
        int c4 = (lin & 15) << 2;
        float4 v = make_float4(0.f, 0.f, 0.f, 0.f);
        if (row < valid) v = *(const float4*)(X + (size_t)(base + row) * D + c4);
        __nv_bfloat16 h0, l0, h1, l1, h2, l2, h3, l3;
        split2(v.x, h0, l0); split2(v.y, h1, l1); split2(v.z, h2, l2); split2(v.w, h3, l3);
        __nv_bfloat162* ph = (__nv_bfloat162*)(Xh + row * XSTR + c4);
        __nv_bfloat162* pl = (__nv_bfloat162*)(Xl + row * XSTR + c4);
        ph[0] = __nv_bfloat162(h0, h1); ph[1] = __nv_bfloat162(h2, h3);
        pl[0] = __nv_bfloat162(l0, l1); pl[1] = __nv_bfloat162(l2, l3);
    }
    // both weight layers preloaded before the single barrier
    load_w_split(W1, W1h, W1l, tid);
    load_w_split(W2, W2h, W2l, tid);
    __syncthreads();

    float acc[2][8][4];
    do_layer(Xh, Xl, W1h, b1, acc, warp, lane);

    // relu + split H back into Xh/Xl. A-fragments are warp-private (warp w only
    // ever reads rows [32w,32w+32)), so no block barrier is needed — only a
    // __syncwarp to order cross-lane STS before ldmatrix.
#pragma unroll
    for (int mt = 0; mt < 2; mt++) {
#pragma unroll
        for (int nt = 0; nt < 8; nt++) {
            int ra = warp * 32 + mt * 16 + g;
            int col = nt * 8 + 2 * qp;
            float v0 = fmaxf(acc[mt][nt][0], 0.f);
            float v1 = fmaxf(acc[mt][nt][1], 0.f);
            float v2 = fmaxf(acc[mt][nt][2], 0.f);
            float v3 = fmaxf(acc[mt][nt][3], 0.f);
            __nv_bfloat16 h0, l0, h1, l1, h2, l2, h3, l3;
            split2(v0, h0, l0); split2(v1, h1, l1);
            split2(v2, h2, l2); split2(v3, h3, l3);
            *(__nv_bfloat162*)(Xh + ra * XSTR + col) = __nv_bfloat162(h0, h1);
            *(__nv_bfloat162*)(Xl + ra * XSTR + col) = __nv_bfloat162(l0, l1);
            *(__nv_bfloat162*)(Xh + (ra + 8) * XSTR + col) = __nv_bfloat162(h2, h3);
            *(__nv_bfloat162*)(Xl + (ra + 8) * XSTR + col) = __nv_bfloat162(l2, l3);
        }
    }
    __syncwarp();

    do_layer(Xh, Xl, W2h, b2, acc, warp, lane);

    // write Y (fp16) + block BN stats (fp32 accs)
#pragma unroll
    for (int mt = 0; mt < 2; mt++) {
#pragma unroll
        for (int nt = 0; nt < 8; nt++) {
            int ra = base + warp * 32 + mt * 16 + g;
            int rb = ra + 8;
            int col = nt * 8 + 2 * qp;
            float c0 = acc[mt][nt][0], c1 = acc[mt][nt][1];
            float c2 = acc[mt][nt][2], c3 = acc[mt][nt][3];
            bool va = ra < nrows, vb = rb < nrows;
            if (va) *(__half2*)(Y + (size_t)ra * D + col) = __floats2half2_rn(c0, c1);
            if (vb) *(__half2*)(Y + (size_t)rb * D + col) = __floats2half2_rn(c2, c3);
            float s0 = (va ? c0 : 0.f) + (vb ? c2 : 0.f);
            float s1 = (va ? c1 : 0.f) + (vb ? c3 : 0.f);
            float q0 = (va ? c0 * c0 : 0.f) + (vb ? c2 * c2 : 0.f);
            float q1 = (va ? c1 * c1 : 0.f) + (vb ? c3 * c3 : 0.f);
#pragma unroll
            for (int off = 4; off < 32; off <<= 1) {
                s0 += __shfl_xor_sync(0xffffffffu, s0, off);
                s1 += __shfl_xor_sync(0xffffffffu, s1, off);
                q0 += __shfl_xor_sync(0xffffffffu, q0, off);
                q1 += __shfl_xor_sync(0xffffffffu, q1, off);
            }
            if (lane < 4) {               // lane == qp group representative
                atomicAdd(sstat + col, s0);
                atomicAdd(sstat + col + 1, s1);
                atomicAdd(sstat + 64 + col, q0);
                atomicAdd(sstat + 64 + col + 1, q1);
            }
        }
    }
    __syncthreads();
    if (tid < D) {
        int slot = blockIdx.x & (NSLOT - 1);
        float* p = g_partial + ((path * NSLOT + slot) * 2) * D;
        atomicAdd(p + tid, sstat[tid]);
        atomicAdd(p + D + tid, sstat[64 + tid]);
    }
}

// ---------------- K4: finalize BN -> per-column scale/shift ----------------
__global__ void k_finalize(const float* __restrict__ gamma_h, const float* __restrict__ beta_h,
                           const float* __restrict__ gamma_e, const float* __restrict__ beta_e,
                           int n_nodes, int n_edges) {
    int t = threadIdx.x;            // 128 threads
    int path = t >> 6;
    int col = t & 63;
    float n = (path == 0) ? (float)n_nodes : (float)n_edges;
    float s = 0.f, q = 0.f;
    for (int slot = 0; slot < NSLOT; slot++) {
        const float* p = g_partial + ((path * NSLOT + slot) * 2) * D;
        s += p[col];
        q += p[D + col];
    }
    float mean = s / n;
    float var = q / n - mean * mean;
    float rstd = rsqrtf(var + BN_EPS);
    float gamma = (path == 0) ? __ldg(gamma_h + col) : __ldg(gamma_e + col);
    float beta  = (path == 0) ? __ldg(beta_h + col)  : __ldg(beta_e + col);
    float scale = gamma * rstd;
    float shift = beta - mean * scale;
    g_final[path * 2 * D + col] = scale;
    g_final[path * 2 * D + D + col] = shift;
}

// ---------------- K5/K6: epilogue  out = in + relu(scale*y + shift) ----------------
__global__ void k_epi(const float* __restrict__ inp, int path,
                      float* __restrict__ out, int nrows) {
    int i = blockIdx.x * blockDim.x + threadIdx.x;
    int total4 = nrows * (D / 4);
    if (i >= total4) return;
    const __half* y = (path == 0) ? g_hn : g_en;
    int c4 = (i & 15) * 4;
    const float* sc = g_final + path * 2 * D;
    const float* sh = sc + D;
    const __half2* yp = (const __half2*)(y + (((size_t)i >> 4) << 6) + c4);
    float2 y01 = __half22float2(yp[0]);
    float2 y23 = __half22float2(yp[1]);
    float4 xv = *((const float4*)inp + i);
    float4 o;
    o.x = xv.x + fmaxf(fmaf(sc[c4 + 0], y01.x, sh[c4 + 0]), 0.f);
    o.y = xv.y + fmaxf(fmaf(sc[c4 + 1], y01.y, sh[c4 + 1]), 0.f);
    o.z = xv.z + fmaxf(fmaf(sc[c4 + 2], y23.x, sh[c4 + 2]), 0.f);
    o.w = xv.w + fmaxf(fmaf(sc[c4 + 3], y23.y, sh[c4 + 3]), 0.f);
    *((float4*)out + i) = o;
}

// ---------------- launch ----------------
static cudaStream_t g_s2 = nullptr;
static cudaEvent_t g_ev0, g_ev1, g_ev2, g_ev3;

extern "C" void kernel_launch(void* const* d_in, const int* in_sizes, int n_in,
                              void* d_out, int out_size) {
    if (g_s2 == nullptr) {   // one-time resource creation (host-side, not captured work)
        cudaStreamCreateWithFlags(&g_s2, cudaStreamNonBlocking);
        cudaEventCreateWithFlags(&g_ev0, cudaEventDisableTiming);
        cudaEventCreateWithFlags(&g_ev1, cudaEventDisableTiming);
        cudaEventCreateWithFlags(&g_ev2, cudaEventDisableTiming);
        cudaEventCreateWithFlags(&g_ev3, cudaEventDisableTiming);
    }

    const float* h   = (const float*)d_in[0];
    const float* e   = (const float*)d_in[1];
    const int*   src = (const int*)d_in[2];
    const int*   dst = (const int*)d_in[3];
    const float* eps = (const float*)d_in[4];
    const float* W1  = (const float*)d_in[5];
    const float* b1  = (const float*)d_in[6];
    const float* W2  = (const float*)d_in[7];
    const float* b2  = (const float*)d_in[8];
    const float* gh  = (const float*)d_in[9];
    const float* bh  = (const float*)d_in[10];
    const float* ge  = (const float*)d_in[11];
    const float* be  = (const float*)d_in[12];

    int n_nodes = in_sizes[0] / D;
    int n_edges = in_sizes[1] / D;
    float* out = (float*)d_out;
    float* out_h = out;
    float* out_e = out + (size_t)n_nodes * D;

    int t4n = n_nodes * (D / 4);
    int t4e = n_edges * (D / 4);

    // X(hi+lo) + 2 weight layers (hi+lo) + stats
    const int SMEM_BYTES = (2 * TROWS * XSTR + 4 * D * WSTR) * 2 + 2 * D * 4;  // 111104
    cudaFuncSetAttribute(k_mlp_tc, cudaFuncAttributeMaxDynamicSharedMemorySize, SMEM_BYTES);

    // ---- fork: edge chain (zero edge partials -> edge MLP) on side stream ----
    cudaEventRecord(g_ev0, 0);
    cudaStreamWaitEvent(g_s2, g_ev0, 0);
    k_zero_e<<<(NSLOT * 2 * D + 255) / 256, 256, 0, g_s2>>>();
    k_mlp_tc<<<(n_edges + TROWS - 1) / TROWS, 256, SMEM_BYTES, g_s2>>>(
        e, W1, b1, W2, b2, /*src_sel=*/1, /*path=*/1, n_edges);

    // ---- main stream: node chain (init zeroes node partials only) ----
    k_init<<<(t4n + 255) / 256, 256>>>(h, eps, n_nodes);
    {
        long long threads = (long long)n_edges * 16;
        int blocks = (int)((threads + 255) / 256);
        k_scatter<<<blocks, 256>>>(h, src, dst, n_edges);
    }
    k_mlp_tc<<<(n_nodes + TROWS - 1) / TROWS, 256, SMEM_BYTES>>>(
        nullptr, W1, b1, W2, b2, /*src_sel=*/0, /*path=*/0, n_nodes);

    // ---- join: both stat sets complete before finalize ----
    cudaEventRecord(g_ev1, g_s2);
    cudaStreamWaitEvent(0, g_ev1, 0);
    k_finalize<<<1, 128>>>(gh, bh, ge, be, n_nodes, n_edges);

    // ---- fork epilogues: node epi on side stream, edge epi on main ----
    cudaEventRecord(g_ev2, 0);
    cudaStreamWaitEvent(g_s2, g_ev2, 0);
    k_epi<<<(t4n + 255) / 256, 256, 0, g_s2>>>(h, /*path=*/0, out_h, n_nodes);
    k_epi<<<(t4e + 255) / 256, 256>>>(e, /*path=*/1, out_e, n_edges);
    cudaEventRecord(g_ev3, g_s2);
    cudaStreamWaitEvent(0, g_ev3, 0);
}

// round 14
// speedup vs baseline: 1.9698x; 1.1018x over previous
#include <cuda_runtime.h>
#include <cuda_bf16.h>
#include <cuda_fp16.h>

#define D 64
#define MAXN 100000
#define MAXE 1600000
#define BN_EPS 1e-5f
#define NSLOT 32

#define TROWS 256          // rows per MLP block
#define XSTR 72            // padded fp16 row stride (144B) -> conflict-free ldmatrix
#define WSTR 72

// ---------------- scratch (static __device__, allocation-free) ----------------
static __device__ float  g_acc[(size_t)MAXN * D];             // (1+eps)*h + scatter-sum
static __device__ __half g_hn[(size_t)MAXN * D];              // MLP(node) pre-norm (fp16)
static __device__ __half g_en[(size_t)MAXE * D];              // MLP(edge) pre-norm (fp16)
static __device__ float g_partial[2 * NSLOT * 2 * D];         // [path][slot][sum|sumsq][col]
static __device__ float g_final[4 * D];                       // [path][scale|shift][col]

// ---------------- K0: init accumulator + zero NODE stat partials only ----------------
__global__ void k_init(const float* __restrict__ h, const float* __restrict__ eps,
                       int n_nodes) {
    int i = blockIdx.x * blockDim.x + threadIdx.x;
    int total4 = n_nodes * (D / 4);
    if (i < total4) {
        float s = 1.0f + __ldg(eps);
        float4 v = *((const float4*)h + i);
        v.x *= s; v.y *= s; v.z *= s; v.w *= s;
        *((float4*)g_acc + i) = v;
    }
    if (i < NSLOT * 2 * D) g_partial[i] = 0.0f;          // path-0 (node) slots only
}

// ---------------- K0b (side stream): zero EDGE stat partials ----------------
__global__ void k_zero_e() {
    int i = blockIdx.x * blockDim.x + threadIdx.x;
    if (i < NSLOT * 2 * D) g_partial[NSLOT * 2 * D + i] = 0.0f;   // path-1 (edge) slots
}

// ---------------- K1: scatter-add h[src] onto acc[dst] (vector red) ----------------
__global__ void k_scatter(const float* __restrict__ h, const int* __restrict__ src,
                          const int* __restrict__ dst, int n_edges) {
    long long t = (long long)blockIdx.x * blockDim.x + threadIdx.x;
    int e = (int)(t >> 4);
    if (e >= n_edges) return;
    int part = ((int)t & 15) * 4;
    int s = __ldg(src + e);
    int d = __ldg(dst + e);
    const float4 v = *(const float4*)(h + (size_t)s * D + part);
    float* p = g_acc + (size_t)d * D + part;
    asm volatile("red.global.add.v4.f32 [%0], {%1,%2,%3,%4};"
                 :: "l"(p), "f"(v.x), "f"(v.y), "f"(v.z), "f"(v.w) : "memory");
}

// ---------------- tensor-core MLP helpers (fp16, 2-term split) ----------------
__device__ __forceinline__ void ldmA(unsigned* a, const __half* p) {
    unsigned addr = (unsigned)__cvta_generic_to_shared(p);
    asm volatile("ldmatrix.sync.aligned.m8n8.x4.shared.b16 {%0,%1,%2,%3}, [%4];"
                 : "=r"(a[0]), "=r"(a[1]), "=r"(a[2]), "=r"(a[3]) : "r"(addr));
}
// x4.trans: one instruction loads B fragments for TWO adjacent n-tiles (16 cols).
// lanes 0-15 address rows of cols [0,8); lanes 16-31 rows of cols [8,16).
__device__ __forceinline__ void ldmB4(unsigned* b, const __half* p) {
    unsigned addr = (unsigned)__cvta_generic_to_shared(p);
    asm volatile("ldmatrix.sync.aligned.m8n8.x4.trans.shared.b16 {%0,%1,%2,%3}, [%4];"
                 : "=r"(b[0]), "=r"(b[1]), "=r"(b[2]), "=r"(b[3]) : "r"(addr));
}
__device__ __forceinline__ void mma_f16(float* c, const unsigned* a, const unsigned* b) {
    asm volatile("mma.sync.aligned.m16n8k16.row.col.f32.f16.f16.f32 "
                 "{%0,%1,%2,%3}, {%4,%5,%6,%7}, {%8,%9}, {%0,%1,%2,%3};"
                 : "+f"(c[0]), "+f"(c[1]), "+f"(c[2]), "+f"(c[3])
                 : "r"(a[0]), "r"(a[1]), "r"(a[2]), "r"(a[3]), "r"(b[0]), "r"(b[1]));
}
__device__ __forceinline__ void split2h(float x, __half& hi, __half& lo) {
    hi = __float2half_rn(x);
    lo = __float2half_rn(x - __half2float(hi));
}

// single-precision-ish weights: one fp16 tile (w error ~2^-12, covered by threshold)
__device__ __forceinline__ void load_w_h(const float* __restrict__ W,
                                         __half* Wd, int tid) {
#pragma unroll
    for (int i = 0; i < 4; i++) {
        int lin = tid + i * 256;          // 1024 float4 = 64 x 16
        int k = lin >> 4;
        int c4 = (lin & 15) << 2;
        float4 v = *(const float4*)(W + k * D + c4);
        __half2* pd = (__half2*)(Wd + k * WSTR + c4);
        pd[0] = __floats2half2_rn(v.x, v.y);
        pd[1] = __floats2half2_rn(v.z, v.w);
    }
}

// one 64x64 layer for this warp's 32 rows: acc = X(rows) @ W + bias
// 2 MMAs per tile: (x_hi + x_lo) * w   [x exact in fp16x2, w fp16]
__device__ __forceinline__ void do_layer(const __half* Xh, const __half* Xl,
                                         const __half* Wd,
                                         const float* __restrict__ bias,
                                         float acc[2][8][4], int warp, int lane) {
    int qp = lane & 3;
#pragma unroll
    for (int nt = 0; nt < 8; nt++) {
        float bv0 = __ldg(bias + nt * 8 + 2 * qp);
        float bv1 = __ldg(bias + nt * 8 + 2 * qp + 1);
#pragma unroll
        for (int mt = 0; mt < 2; mt++) {
            acc[mt][nt][0] = bv0; acc[mt][nt][1] = bv1;
            acc[mt][nt][2] = bv0; acc[mt][nt][3] = bv1;
        }
    }
    int rowbase = warp * 32;
    int arow = lane & 15;
    int akoff = (lane >> 4) * 8;
    // lanes 0-15: rows of first 8-col tile; lanes 16-31: rows of second 8-col tile
    const __half* wlane = Wd + (lane & 15) * WSTR + (lane >> 4) * 8;
#pragma unroll
    for (int kk = 0; kk < 4; kk++) {
        unsigned a1[2][4], a2[2][4];
#pragma unroll
        for (int mt = 0; mt < 2; mt++) {
            ldmA(a1[mt], Xh + (rowbase + mt * 16 + arow) * XSTR + kk * 16 + akoff);
            ldmA(a2[mt], Xl + (rowbase + mt * 16 + arow) * XSTR + kk * 16 + akoff);
        }
#pragma unroll
        for (int nt2 = 0; nt2 < 4; nt2++) {
            unsigned b[4];                      // {b(nt even) , b(nt odd)}
            ldmB4(b, wlane + kk * 16 * WSTR + nt2 * 16);
#pragma unroll
            for (int mt = 0; mt < 2; mt++) {
                mma_f16(acc[mt][2 * nt2 + 0], a1[mt], b + 0);   // x_hi * w
                mma_f16(acc[mt][2 * nt2 + 0], a2[mt], b + 0);   // x_lo * w
                mma_f16(acc[mt][2 * nt2 + 1], a1[mt], b + 2);
                mma_f16(acc[mt][2 * nt2 + 1], a2[mt], b + 2);
            }
        }
    }
}

// ---------------- K2/K3: tensor-core fused 2-layer MLP + BN stats ----------------
__global__ __launch_bounds__(256, 2)
void k_mlp_tc(const float* __restrict__ Xext,
              const float* __restrict__ W1, const float* __restrict__ b1,
              const float* __restrict__ W2, const float* __restrict__ b2,
              int src_sel, int path, int nrows) {
    extern __shared__ char smem_raw[];
    __half* Xh  = (__half*)smem_raw;
    __half* Xl  = Xh  + TROWS * XSTR;
    __half* W1d = Xl  + TROWS * XSTR;
    __half* W2d = W1d + D * WSTR;
    float* sstat = (float*)(W2d + D * WSTR);   // [sum(64) | sumsq(64)]

    const float* X = (src_sel == 0) ? g_acc : Xext;
    __half* Y = (path == 0) ? g_hn : g_en;

    int tid = threadIdx.x;
    int warp = tid >> 5;
    int lane = tid & 31;
    int g = lane >> 2;
    int qp = lane & 3;
    int base = blockIdx.x * TROWS;
    int valid = nrows - base; if (valid > TROWS) valid = TROWS;

    if (tid < 2 * D) sstat[tid] = 0.f;

    // load X tile, split into fp16 hi/lo (zero-pad invalid rows)
#pragma unroll
    for (int i = 0; i < 16; i++) {
        int lin = tid + i * 256;          // 4096 float4 = 256 rows x 16
        int row = lin >> 4;
        int c4 = (lin & 15) << 2;
        float4 v = make_float4(0.f, 0.f, 0.f, 0.f);
        if (row < valid) v = *(const float4*)(X + (size_t)(base + row) * D + c4);
        __half h0, l0, h1, l1, h2, l2, h3, l3;
        split2h(v.x, h0, l0); split2h(v.y, h1, l1);
        split2h(v.z, h2, l2); split2h(v.w, h3, l3);
        __half2* ph = (__half2*)(Xh + row * XSTR + c4);
        __half2* pl = (__half2*)(Xl + row * XSTR + c4);
        ph[0] = __half2(h0, h1); ph[1] = __half2(h2, h3);
        pl[0] = __half2(l0, l1); pl[1] = __half2(l2, l3);
    }
    // both weight layers preloaded before the single barrier
    load_w_h(W1, W1d, tid);
    load_w_h(W2, W2d, tid);
    __syncthreads();

    float acc[2][8][4];
    do_layer(Xh, Xl, W1d, b1, acc, warp, lane);

    // relu + split H back into Xh/Xl. A-rows are warp-private (warp w only reads
    // rows [32w,32w+32)), so only a __syncwarp is needed before ldmatrix.
#pragma unroll
    for (int mt = 0; mt < 2; mt++) {
#pragma unroll
        for (int nt = 0; nt < 8; nt++) {
            int ra = warp * 32 + mt * 16 + g;
            int col = nt * 8 + 2 * qp;
            float v0 = fmaxf(acc[mt][nt][0], 0.f);
            float v1 = fmaxf(acc[mt][nt][1], 0.f);
            float v2 = fmaxf(acc[mt][nt][2], 0.f);
            float v3 = fmaxf(acc[mt][nt][3], 0.f);
            __half h0, l0, h1, l1, h2, l2, h3, l3;
            split2h(v0, h0, l0); split2h(v1, h1, l1);
            split2h(v2, h2, l2); split2h(v3, h3, l3);
            *(__half2*)(Xh + ra * XSTR + col) = __half2(h0, h1);
            *(__half2*)(Xl + ra * XSTR + col) = __half2(l0, l1);
            *(__half2*)(Xh + (ra + 8) * XSTR + col) = __half2(h2, h3);
            *(__half2*)(Xl + (ra + 8) * XSTR + col) = __half2(l2, l3);
        }
    }
    __syncwarp();

    do_layer(Xh, Xl, W2d, b2, acc, warp, lane);

    // write Y (fp16) + block BN stats (fp32 accs)
#pragma unroll
    for (int mt = 0; mt < 2; mt++) {
#pragma unroll
        for (int nt = 0; nt < 8; nt++) {
            int ra = base + warp * 32 + mt * 16 + g;
            int rb = ra + 8;
            int col = nt * 8 + 2 * qp;
            float c0 = acc[mt][nt][0], c1 = acc[mt][nt][1];
            float c2 = acc[mt][nt][2], c3 = acc[mt][nt][3];
            bool va = ra < nrows, vb = rb < nrows;
            if (va) *(__half2*)(Y + (size_t)ra * D + col) = __floats2half2_rn(c0, c1);
            if (vb) *(__half2*)(Y + (size_t)rb * D + col) = __floats2half2_rn(c2, c3);
            float s0 = (va ? c0 : 0.f) + (vb ? c2 : 0.f);
            float s1 = (va ? c1 : 0.f) + (vb ? c3 : 0.f);
            float q0 = (va ? c0 * c0 : 0.f) + (vb ? c2 * c2 : 0.f);
            float q1 = (va ? c1 * c1 : 0.f) + (vb ? c3 * c3 : 0.f);
#pragma unroll
            for (int off = 4; off < 32; off <<= 1) {
                s0 += __shfl_xor_sync(0xffffffffu, s0, off);
                s1 += __shfl_xor_sync(0xffffffffu, s1, off);
                q0 += __shfl_xor_sync(0xffffffffu, q0, off);
                q1 += __shfl_xor_sync(0xffffffffu, q1, off);
            }
            if (lane < 4) {               // lane == qp group representative
                atomicAdd(sstat + col, s0);
                atomicAdd(sstat + col + 1, s1);
                atomicAdd(sstat + 64 + col, q0);
                atomicAdd(sstat + 64 + col + 1, q1);
            }
        }
    }
    __syncthreads();
    if (tid < D) {
        int slot = blockIdx.x & (NSLOT - 1);
        float* p = g_partial + ((path * NSLOT + slot) * 2) * D;
        atomicAdd(p + tid, sstat[tid]);
        atomicAdd(p + D + tid, sstat[64 + tid]);
    }
}

// ---------------- K4: finalize BN -> per-column scale/shift ----------------
__global__ void k_finalize(const float* __restrict__ gamma_h, const float* __restrict__ beta_h,
                           const float* __restrict__ gamma_e, const float* __restrict__ beta_e,
                           int n_nodes, int n_edges) {
    int t = threadIdx.x;            // 128 threads
    int path = t >> 6;
    int col = t & 63;
    float n = (path == 0) ? (float)n_nodes : (float)n_edges;
    float s = 0.f, q = 0.f;
    for (int slot = 0; slot < NSLOT; slot++) {
        const float* p = g_partial + ((path * NSLOT + slot) * 2) * D;
        s += p[col];
        q += p[D + col];
    }
    float mean = s / n;
    float var = q / n - mean * mean;
    float rstd = rsqrtf(var + BN_EPS);
    float gamma = (path == 0) ? __ldg(gamma_h + col) : __ldg(gamma_e + col);
    float beta  = (path == 0) ? __ldg(beta_h + col)  : __ldg(beta_e + col);
    float scale = gamma * rstd;
    float shift = beta - mean * scale;
    g_final[path * 2 * D + col] = scale;
    g_final[path * 2 * D + D + col] = shift;
}

// ---------------- K5/K6: epilogue  out = in + relu(scale*y + shift) ----------------
__global__ void k_epi(const float* __restrict__ inp, int path,
                      float* __restrict__ out, int nrows) {
    int i = blockIdx.x * blockDim.x + threadIdx.x;
    int total4 = nrows * (D / 4);
    if (i >= total4) return;
    const __half* y = (path == 0) ? g_hn : g_en;
    int c4 = (i & 15) * 4;
    const float* sc = g_final + path * 2 * D;
    const float* sh = sc + D;
    const __half2* yp = (const __half2*)(y + (((size_t)i >> 4) << 6) + c4);
    float2 y01 = __half22float2(yp[0]);
    float2 y23 = __half22float2(yp[1]);
    float4 xv = *((const float4*)inp + i);
    float4 o;
    o.x = xv.x + fmaxf(fmaf(sc[c4 + 0], y01.x, sh[c4 + 0]), 0.f);
    o.y = xv.y + fmaxf(fmaf(sc[c4 + 1], y01.y, sh[c4 + 1]), 0.f);
    o.z = xv.z + fmaxf(fmaf(sc[c4 + 2], y23.x, sh[c4 + 2]), 0.f);
    o.w = xv.w + fmaxf(fmaf(sc[c4 + 3], y23.y, sh[c4 + 3]), 0.f);
    *((float4*)out + i) = o;
}

// ---------------- launch ----------------
static cudaStream_t g_s2 = nullptr;
static cudaEvent_t g_ev0, g_ev1, g_ev2, g_ev3;

extern "C" void kernel_launch(void* const* d_in, const int* in_sizes, int n_in,
                              void* d_out, int out_size) {
    if (g_s2 == nullptr) {   // one-time resource creation (host-side, not captured work)
        cudaStreamCreateWithFlags(&g_s2, cudaStreamNonBlocking);
        cudaEventCreateWithFlags(&g_ev0, cudaEventDisableTiming);
        cudaEventCreateWithFlags(&g_ev1, cudaEventDisableTiming);
        cudaEventCreateWithFlags(&g_ev2, cudaEventDisableTiming);
        cudaEventCreateWithFlags(&g_ev3, cudaEventDisableTiming);
    }

    const float* h   = (const float*)d_in[0];
    const float* e   = (const float*)d_in[1];
    const int*   src = (const int*)d_in[2];
    const int*   dst = (const int*)d_in[3];
    const float* eps = (const float*)d_in[4];
    const float* W1  = (const float*)d_in[5];
    const float* b1  = (const float*)d_in[6];
    const float* W2  = (const float*)d_in[7];
    const float* b2  = (const float*)d_in[8];
    const float* gh  = (const float*)d_in[9];
    const float* bh  = (const float*)d_in[10];
    const float* ge  = (const float*)d_in[11];
    const float* be  = (const float*)d_in[12];

    int n_nodes = in_sizes[0] / D;
    int n_edges = in_sizes[1] / D;
    float* out = (float*)d_out;
    float* out_h = out;
    float* out_e = out + (size_t)n_nodes * D;

    int t4n = n_nodes * (D / 4);
    int t4e = n_edges * (D / 4);

    // X(hi+lo) + 2 fp16 weight tiles + stats
    const int SMEM_BYTES = (2 * TROWS * XSTR + 2 * D * WSTR) * 2 + 2 * D * 4;  // 92672
    cudaFuncSetAttribute(k_mlp_tc, cudaFuncAttributeMaxDynamicSharedMemorySize, SMEM_BYTES);

    // ---- fork: edge chain (zero edge partials -> edge MLP) on side stream ----
    cudaEventRecord(g_ev0, 0);
    cudaStreamWaitEvent(g_s2, g_ev0, 0);
    k_zero_e<<<(NSLOT * 2 * D + 255) / 256, 256, 0, g_s2>>>();
    k_mlp_tc<<<(n_edges + TROWS - 1) / TROWS, 256, SMEM_BYTES, g_s2>>>(
        e, W1, b1, W2, b2, /*src_sel=*/1, /*path=*/1, n_edges);

    // ---- main stream: node chain (init zeroes node partials only) ----
    k_init<<<(t4n + 255) / 256, 256>>>(h, eps, n_nodes);
    {
        long long threads = (long long)n_edges * 16;
        int blocks = (int)((threads + 255) / 256);
        k_scatter<<<blocks, 256>>>(h, src, dst, n_edges);
    }
    k_mlp_tc<<<(n_nodes + TROWS - 1) / TROWS, 256, SMEM_BYTES>>>(
        nullptr, W1, b1, W2, b2, /*src_sel=*/0, /*path=*/0, n_nodes);

    // ---- join: both stat sets complete before finalize ----
    cudaEventRecord(g_ev1, g_s2);
    cudaStreamWaitEvent(0, g_ev1, 0);
    k_finalize<<<1, 128>>>(gh, bh, ge, be, n_nodes, n_edges);

    // ---- fork epilogues: node epi on side stream, edge epi on main ----
    cudaEventRecord(g_ev2, 0);
    cudaStreamWaitEvent(g_s2, g_ev2, 0);
    k_epi<<<(t4n + 255) / 256, 256, 0, g_s2>>>(h, /*path=*/0, out_h, n_nodes);
    k_epi<<<(t4e + 255) / 256, 256>>>(e, /*path=*/1, out_e, n_edges);
    cudaEventRecord(g_ev3, g_s2);
    cudaStreamWaitEvent(0, g_ev3, 0);
}

// round 15
// speedup vs baseline: 2.1088x; 1.0705x over previous
#include <cuda_runtime.h>
#include <cuda_bf16.h>
#include <cuda_fp16.h>

#define D 64
#define MAXN 100000
#define MAXE 1600000
#define BN_EPS 1e-5f
#define NSLOT 32

#define TROWS 256          // rows per MLP block
#define XSTR 72            // padded fp16 row stride (144B) -> conflict-free ldmatrix
#define WSTR 72

// ---------------- scratch (static __device__, allocation-free) ----------------
static __device__ float  g_acc[(size_t)MAXN * D];             // (1+eps)*h + scatter-sum
static __device__ __half g_hn[(size_t)MAXN * D];              // MLP(node) pre-norm (fp16)
static __device__ __half g_en[(size_t)MAXE * D];              // MLP(edge) pre-norm (fp16)
static __device__ float g_partial[2 * NSLOT * 2 * D];         // [path][slot][sum|sumsq][col]
static __device__ float g_final[4 * D];                       // [path][scale|shift][col]

// ---------------- K0: init accumulator + zero NODE stat partials only ----------------
__global__ void k_init(const float* __restrict__ h, const float* __restrict__ eps,
                       int n_nodes) {
    int i = blockIdx.x * blockDim.x + threadIdx.x;
    int total4 = n_nodes * (D / 4);
    if (i < total4) {
        float s = 1.0f + __ldg(eps);
        float4 v = *((const float4*)h + i);
        v.x *= s; v.y *= s; v.z *= s; v.w *= s;
        *((float4*)g_acc + i) = v;
    }
    if (i < NSLOT * 2 * D) g_partial[i] = 0.0f;          // path-0 (node) slots only
}

// ---------------- K0b (side stream): zero EDGE stat partials ----------------
__global__ void k_zero_e() {
    int i = blockIdx.x * blockDim.x + threadIdx.x;
    if (i < NSLOT * 2 * D) g_partial[NSLOT * 2 * D + i] = 0.0f;   // path-1 (edge) slots
}

// ---------------- K1: scatter-add h[src] onto acc[dst] (vector red) ----------------
__global__ void k_scatter(const float* __restrict__ h, const int* __restrict__ src,
                          const int* __restrict__ dst, int n_edges) {
    long long t = (long long)blockIdx.x * blockDim.x + threadIdx.x;
    int e = (int)(t >> 4);
    if (e >= n_edges) return;
    int part = ((int)t & 15) * 4;
    int s = __ldg(src + e);
    int d = __ldg(dst + e);
    const float4 v = *(const float4*)(h + (size_t)s * D + part);
    float* p = g_acc + (size_t)d * D + part;
    asm volatile("red.global.add.v4.f32 [%0], {%1,%2,%3,%4};"
                 :: "l"(p), "f"(v.x), "f"(v.y), "f"(v.z), "f"(v.w) : "memory");
}

// ---------------- tensor-core MLP helpers (pure fp16 operands) ----------------
__device__ __forceinline__ void ldmA(unsigned* a, const __half* p) {
    unsigned addr = (unsigned)__cvta_generic_to_shared(p);
    asm volatile("ldmatrix.sync.aligned.m8n8.x4.shared.b16 {%0,%1,%2,%3}, [%4];"
                 : "=r"(a[0]), "=r"(a[1]), "=r"(a[2]), "=r"(a[3]) : "r"(addr));
}
// x4.trans: one instruction loads B fragments for TWO adjacent 8-col n-tiles.
// lanes 0-15 address rows of cols [0,8); lanes 16-31 rows of cols [8,16).
__device__ __forceinline__ void ldmB4(unsigned* b, const __half* p) {
    unsigned addr = (unsigned)__cvta_generic_to_shared(p);
    asm volatile("ldmatrix.sync.aligned.m8n8.x4.trans.shared.b16 {%0,%1,%2,%3}, [%4];"
                 : "=r"(b[0]), "=r"(b[1]), "=r"(b[2]), "=r"(b[3]) : "r"(addr));
}
__device__ __forceinline__ void mma_f16(float* c, const unsigned* a, const unsigned* b) {
    asm volatile("mma.sync.aligned.m16n8k16.row.col.f32.f16.f16.f32 "
                 "{%0,%1,%2,%3}, {%4,%5,%6,%7}, {%8,%9}, {%0,%1,%2,%3};"
                 : "+f"(c[0]), "+f"(c[1]), "+f"(c[2]), "+f"(c[3])
                 : "r"(a[0]), "r"(a[1]), "r"(a[2]), "r"(a[3]), "r"(b[0]), "r"(b[1]));
}

// fp16 weight tile (w error ~2^-12, within threshold budget)
__device__ __forceinline__ void load_w_h(const float* __restrict__ W,
                                         __half* Wd, int tid) {
#pragma unroll
    for (int i = 0; i < 4; i++) {
        int lin = tid + i * 256;          // 1024 float4 = 64 x 16
        int k = lin >> 4;
        int c4 = (lin & 15) << 2;
        float4 v = *(const float4*)(W + k * D + c4);
        __half2* pd = (__half2*)(Wd + k * WSTR + c4);
        pd[0] = __floats2half2_rn(v.x, v.y);
        pd[1] = __floats2half2_rn(v.z, v.w);
    }
}

// one 64x64 layer for this warp's 32 rows: acc = X(rows) @ W + bias, 1 MMA/tile
__device__ __forceinline__ void do_layer(const __half* Xs, const __half* Wd,
                                         const float* __restrict__ bias,
                                         float acc[2][8][4], int warp, int lane) {
    int qp = lane & 3;
#pragma unroll
    for (int nt = 0; nt < 8; nt++) {
        float bv0 = __ldg(bias + nt * 8 + 2 * qp);
        float bv1 = __ldg(bias + nt * 8 + 2 * qp + 1);
#pragma unroll
        for (int mt = 0; mt < 2; mt++) {
            acc[mt][nt][0] = bv0; acc[mt][nt][1] = bv1;
            acc[mt][nt][2] = bv0; acc[mt][nt][3] = bv1;
        }
    }
    int rowbase = warp * 32;
    int arow = lane & 15;
    int akoff = (lane >> 4) * 8;
    // lanes 0-15: rows of first 8-col tile; lanes 16-31: rows of second 8-col tile
    const __half* wlane = Wd + (lane & 15) * WSTR + (lane >> 4) * 8;
#pragma unroll
    for (int kk = 0; kk < 4; kk++) {
        unsigned a[2][4];
#pragma unroll
        for (int mt = 0; mt < 2; mt++)
            ldmA(a[mt], Xs + (rowbase + mt * 16 + arow) * XSTR + kk * 16 + akoff);
#pragma unroll
        for (int nt2 = 0; nt2 < 4; nt2++) {
            unsigned b[4];                      // {b(nt even), b(nt odd)}
            ldmB4(b, wlane + kk * 16 * WSTR + nt2 * 16);
#pragma unroll
            for (int mt = 0; mt < 2; mt++) {
                mma_f16(acc[mt][2 * nt2 + 0], a[mt], b + 0);
                mma_f16(acc[mt][2 * nt2 + 1], a[mt], b + 2);
            }
        }
    }
}

// ---------------- K2/K3: tensor-core fused 2-layer MLP + BN stats ----------------
__global__ __launch_bounds__(256, 3)
void k_mlp_tc(const float* __restrict__ Xext,
              const float* __restrict__ W1, const float* __restrict__ b1,
              const float* __restrict__ W2, const float* __restrict__ b2,
              int src_sel, int path, int nrows) {
    extern __shared__ char smem_raw[];
    __half* Xs  = (__half*)smem_raw;
    __half* W1d = Xs  + TROWS * XSTR;
    __half* W2d = W1d + D * WSTR;
    float* sstat = (float*)(W2d + D * WSTR);   // [sum(64) | sumsq(64)]

    const float* X = (src_sel == 0) ? g_acc : Xext;
    __half* Y = (path == 0) ? g_hn : g_en;

    int tid = threadIdx.x;
    int warp = tid >> 5;
    int lane = tid & 31;
    int g = lane >> 2;
    int qp = lane & 3;
    int base = blockIdx.x * TROWS;
    int valid = nrows - base; if (valid > TROWS) valid = TROWS;

    if (tid < 2 * D) sstat[tid] = 0.f;

    // load X tile -> fp16 (zero-pad invalid rows)
#pragma unroll
    for (int i = 0; i < 16; i++) {
        int lin = tid + i * 256;          // 4096 float4 = 256 rows x 16
        int row = lin >> 4;
        int c4 = (lin & 15) << 2;
        float4 v = make_float4(0.f, 0.f, 0.f, 0.f);
        if (row < valid) v = *(const float4*)(X + (size_t)(base + row) * D + c4);
        __half2* ph = (__half2*)(Xs + row * XSTR + c4);
        ph[0] = __floats2half2_rn(v.x, v.y);
        ph[1] = __floats2half2_rn(v.z, v.w);
    }
    // both weight layers preloaded before the single barrier
    load_w_h(W1, W1d, tid);
    load_w_h(W2, W2d, tid);
    __syncthreads();

    float acc[2][8][4];
    do_layer(Xs, W1d, b1, acc, warp, lane);

    // relu -> fp16 H back into Xs. A-rows are warp-private (warp w only reads
    // rows [32w,32w+32)), so only a __syncwarp is needed before ldmatrix.
#pragma unroll
    for (int mt = 0; mt < 2; mt++) {
#pragma unroll
        for (int nt = 0; nt < 8; nt++) {
            int ra = warp * 32 + mt * 16 + g;
            int col = nt * 8 + 2 * qp;
            float v0 = fmaxf(acc[mt][nt][0], 0.f);
            float v1 = fmaxf(acc[mt][nt][1], 0.f);
            float v2 = fmaxf(acc[mt][nt][2], 0.f);
            float v3 = fmaxf(acc[mt][nt][3], 0.f);
            *(__half2*)(Xs + ra * XSTR + col) = __floats2half2_rn(v0, v1);
            *(__half2*)(Xs + (ra + 8) * XSTR + col) = __floats2half2_rn(v2, v3);
        }
    }
    __syncwarp();

    do_layer(Xs, W2d, b2, acc, warp, lane);

    // write Y (fp16) + block BN stats (fp32 accs)
#pragma unroll
    for (int mt = 0; mt < 2; mt++) {
#pragma unroll
        for (int nt = 0; nt < 8; nt++) {
            int ra = base + warp * 32 + mt * 16 + g;
            int rb = ra + 8;
            int col = nt * 8 + 2 * qp;
            float c0 = acc[mt][nt][0], c1 = acc[mt][nt][1];
            float c2 = acc[mt][nt][2], c3 = acc[mt][nt][3];
            bool va = ra < nrows, vb = rb < nrows;
            if (va) *(__half2*)(Y + (size_t)ra * D + col) = __floats2half2_rn(c0, c1);
            if (vb) *(__half2*)(Y + (size_t)rb * D + col) = __floats2half2_rn(c2, c3);
            float s0 = (va ? c0 : 0.f) + (vb ? c2 : 0.f);
            float s1 = (va ? c1 : 0.f) + (vb ? c3 : 0.f);
            float q0 = (va ? c0 * c0 : 0.f) + (vb ? c2 * c2 : 0.f);
            float q1 = (va ? c1 * c1 : 0.f) + (vb ? c3 * c3 : 0.f);
#pragma unroll
            for (int off = 4; off < 32; off <<= 1) {
                s0 += __shfl_xor_sync(0xffffffffu, s0, off);
                s1 += __shfl_xor_sync(0xffffffffu, s1, off);
                q0 += __shfl_xor_sync(0xffffffffu, q0, off);
                q1 += __shfl_xor_sync(0xffffffffu, q1, off);
            }
            if (lane < 4) {               // lane == qp group representative
                atomicAdd(sstat + col, s0);
                atomicAdd(sstat + col + 1, s1);
                atomicAdd(sstat + 64 + col, q0);
                atomicAdd(sstat + 64 + col + 1, q1);
            }
        }
    }
    __syncthreads();
    if (tid < D) {
        int slot = blockIdx.x & (NSLOT - 1);
        float* p = g_partial + ((path * NSLOT + slot) * 2) * D;
        atomicAdd(p + tid, sstat[tid]);
        atomicAdd(p + D + tid, sstat[64 + tid]);
    }
}

// ---------------- K4: finalize BN -> per-column scale/shift ----------------
__global__ void k_finalize(const float* __restrict__ gamma_h, const float* __restrict__ beta_h,
                           const float* __restrict__ gamma_e, const float* __restrict__ beta_e,
                           int n_nodes, int n_edges) {
    int t = threadIdx.x;            // 128 threads
    int path = t >> 6;
    int col = t & 63;
    float n = (path == 0) ? (float)n_nodes : (float)n_edges;
    float s = 0.f, q = 0.f;
    for (int slot = 0; slot < NSLOT; slot++) {
        const float* p = g_partial + ((path * NSLOT + slot) * 2) * D;
        s += p[col];
        q += p[D + col];
    }
    float mean = s / n;
    float var = q / n - mean * mean;
    float rstd = rsqrtf(var + BN_EPS);
    float gamma = (path == 0) ? __ldg(gamma_h + col) : __ldg(gamma_e + col);
    float beta  = (path == 0) ? __ldg(beta_h + col)  : __ldg(beta_e + col);
    float scale = gamma * rstd;
    float shift = beta - mean * scale;
    g_final[path * 2 * D + col] = scale;
    g_final[path * 2 * D + D + col] = shift;
}

// ---------------- K5/K6: epilogue  out = in + relu(scale*y + shift) ----------------
__global__ void k_epi(const float* __restrict__ inp, int path,
                      float* __restrict__ out, int nrows) {
    int i = blockIdx.x * blockDim.x + threadIdx.x;
    int total4 = nrows * (D / 4);
    if (i >= total4) return;
    const __half* y = (path == 0) ? g_hn : g_en;
    int c4 = (i & 15) * 4;
    const float* sc = g_final + path * 2 * D;
    const float* sh = sc + D;
    const __half2* yp = (const __half2*)(y + (((size_t)i >> 4) << 6) + c4);
    float2 y01 = __half22float2(yp[0]);
    float2 y23 = __half22float2(yp[1]);
    float4 xv = *((const float4*)inp + i);
    float4 o;
    o.x = xv.x + fmaxf(fmaf(sc[c4 + 0], y01.x, sh[c4 + 0]), 0.f);
    o.y = xv.y + fmaxf(fmaf(sc[c4 + 1], y01.y, sh[c4 + 1]), 0.f);
    o.z = xv.z + fmaxf(fmaf(sc[c4 + 2], y23.x, sh[c4 + 2]), 0.f);
    o.w = xv.w + fmaxf(fmaf(sc[c4 + 3], y23.y, sh[c4 + 3]), 0.f);
    *((float4*)out + i) = o;
}

// ---------------- launch ----------------
static cudaStream_t g_s2 = nullptr;
static cudaEvent_t g_ev0, g_ev1, g_ev2, g_ev3;

extern "C" void kernel_launch(void* const* d_in, const int* in_sizes, int n_in,
                              void* d_out, int out_size) {
    if (g_s2 == nullptr) {   // one-time resource creation (host-side, not captured work)
        cudaStreamCreateWithFlags(&g_s2, cudaStreamNonBlocking);
        cudaEventCreateWithFlags(&g_ev0, cudaEventDisableTiming);
        cudaEventCreateWithFlags(&g_ev1, cudaEventDisableTiming);
        cudaEventCreateWithFlags(&g_ev2, cudaEventDisableTiming);
        cudaEventCreateWithFlags(&g_ev3, cudaEventDisableTiming);
    }

    const float* h   = (const float*)d_in[0];
    const float* e   = (const float*)d_in[1];
    const int*   src = (const int*)d_in[2];
    const int*   dst = (const int*)d_in[3];
    const float* eps = (const float*)d_in[4];
    const float* W1  = (const float*)d_in[5];
    const float* b1  = (const float*)d_in[6];
    const float* W2  = (const float*)d_in[7];
    const float* b2  = (const float*)d_in[8];
    const float* gh  = (const float*)d_in[9];
    const float* bh  = (const float*)d_in[10];
    const float* ge  = (const float*)d_in[11];
    const float* be  = (const float*)d_in[12];

    int n_nodes = in_sizes[0] / D;
    int n_edges = in_sizes[1] / D;
    float* out = (float*)d_out;
    float* out_h = out;
    float* out_e = out + (size_t)n_nodes * D;

    int t4n = n_nodes * (D / 4);
    int t4e = n_edges * (D / 4);

    // X + 2 fp16 weight tiles + stats
    const int SMEM_BYTES = (TROWS * XSTR + 2 * D * WSTR) * 2 + 2 * D * 4;  // 55808
    cudaFuncSetAttribute(k_mlp_tc, cudaFuncAttributeMaxDynamicSharedMemorySize, SMEM_BYTES);

    // ---- fork: edge chain (zero edge partials -> edge MLP) on side stream ----
    cudaEventRecord(g_ev0, 0);
    cudaStreamWaitEvent(g_s2, g_ev0, 0);
    k_zero_e<<<(NSLOT * 2 * D + 255) / 256, 256, 0, g_s2>>>();
    k_mlp_tc<<<(n_edges + TROWS - 1) / TROWS, 256, SMEM_BYTES, g_s2>>>(
        e, W1, b1, W2, b2, /*src_sel=*/1, /*path=*/1, n_edges);

    // ---- main stream: node chain (init zeroes node partials only) ----
    k_init<<<(t4n + 255) / 256, 256>>>(h, eps, n_nodes);
    {
        long long threads = (long long)n_edges * 16;
        int blocks = (int)((threads + 255) / 256);
        k_scatter<<<blocks, 256>>>(h, src, dst, n_edges);
    }
    k_mlp_tc<<<(n_nodes + TROWS - 1) / TROWS, 256, SMEM_BYTES>>>(
        nullptr, W1, b1, W2, b2, /*src_sel=*/0, /*path=*/0, n_nodes);

    // ---- join: both stat sets complete before finalize ----
    cudaEventRecord(g_ev1, g_s2);
    cudaStreamWaitEvent(0, g_ev1, 0);
    k_finalize<<<1, 128>>>(gh, bh, ge, be, n_nodes, n_edges);

    // ---- fork epilogues: node epi on side stream, edge epi on main ----
    cudaEventRecord(g_ev2, 0);
    cudaStreamWaitEvent(g_s2, g_ev2, 0);
    k_epi<<<(t4n + 255) / 256, 256, 0, g_s2>>>(h, /*path=*/0, out_h, n_nodes);
    k_epi<<<(t4e + 255) / 256, 256>>>(e, /*path=*/1, out_e, n_edges);
    cudaEventRecord(g_ev3, g_s2);
    cudaStreamWaitEvent(0, g_ev3, 0);
}

// round 17
// speedup vs baseline: 2.1769x; 1.0323x over previous
#include <cuda_runtime.h>
#include <cuda_bf16.h>
#include <cuda_fp16.h>

#define D 64
#define MAXN 100000
#define MAXE 1600000
#define BN_EPS 1e-5f
#define NSLOT 32

#define TROWS 256          // rows per MLP block
#define WSTR 72            // padded fp16 row stride (144B) -> conflict-free ldmatrix

// ---------------- scratch (static __device__, allocation-free) ----------------
static __device__ float  g_acc[(size_t)MAXN * D];             // (1+eps)*h + scatter-sum
static __device__ __half g_hn[(size_t)MAXN * D];              // MLP(node) pre-norm (fp16)
static __device__ __half g_en[(size_t)MAXE * D];              // MLP(edge) pre-norm (fp16)
static __device__ float g_partial[2 * NSLOT * 2 * D];         // [path][slot][sum|sumsq][col]
static __device__ float g_final[4 * D];                       // [path][scale|shift][col]

// ---------------- K0: init accumulator + zero NODE stat partials only ----------------
__global__ void k_init(const float* __restrict__ h, const float* __restrict__ eps,
                       int n_nodes) {
    int i = blockIdx.x * blockDim.x + threadIdx.x;
    int total4 = n_nodes * (D / 4);
    if (i < total4) {
        float s = 1.0f + __ldg(eps);
        float4 v = *((const float4*)h + i);
        v.x *= s; v.y *= s; v.z *= s; v.w *= s;
        *((float4*)g_acc + i) = v;
    }
    if (i < NSLOT * 2 * D) g_partial[i] = 0.0f;          // path-0 (node) slots only
}

// ---------------- K0b (side stream): zero EDGE stat partials ----------------
__global__ void k_zero_e() {
    int i = blockIdx.x * blockDim.x + threadIdx.x;
    if (i < NSLOT * 2 * D) g_partial[NSLOT * 2 * D + i] = 0.0f;   // path-1 (edge) slots
}

// ---------------- K1: scatter-add h[src] onto acc[dst] (vector red) ----------------
__global__ void k_scatter(const float* __restrict__ h, const int* __restrict__ src,
                          const int* __restrict__ dst, int n_edges) {
    long long t = (long long)blockIdx.x * blockDim.x + threadIdx.x;
    int e = (int)(t >> 4);
    if (e >= n_edges) return;
    int part = ((int)t & 15) * 4;
    int s = __ldg(src + e);
    int d = __ldg(dst + e);
    const float4 v = *(const float4*)(h + (size_t)s * D + part);
    float* p = g_acc + (size_t)d * D + part;
    asm volatile("red.global.add.v4.f32 [%0], {%1,%2,%3,%4};"
                 :: "l"(p), "f"(v.x), "f"(v.y), "f"(v.z), "f"(v.w) : "memory");
}

// ---------------- tensor-core MLP helpers (pure fp16 operands) ----------------
// x4.trans: one instruction loads B fragments for TWO adjacent 8-col n-tiles.
__device__ __forceinline__ void ldmB4(unsigned* b, const __half* p) {
    unsigned addr = (unsigned)__cvta_generic_to_shared(p);
    asm volatile("ldmatrix.sync.aligned.m8n8.x4.trans.shared.b16 {%0,%1,%2,%3}, [%4];"
                 : "=r"(b[0]), "=r"(b[1]), "=r"(b[2]), "=r"(b[3]) : "r"(addr));
}
__device__ __forceinline__ void mma_f16(float* c, const unsigned* a, const unsigned* b) {
    asm volatile("mma.sync.aligned.m16n8k16.row.col.f32.f16.f16.f32 "
                 "{%0,%1,%2,%3}, {%4,%5,%6,%7}, {%8,%9}, {%0,%1,%2,%3};"
                 : "+f"(c[0]), "+f"(c[1]), "+f"(c[2]), "+f"(c[3])
                 : "r"(a[0]), "r"(a[1]), "r"(a[2]), "r"(a[3]), "r"(b[0]), "r"(b[1]));
}
__device__ __forceinline__ unsigned packh2(float x, float y) {
    __half2 p = __floats2half2_rn(x, y);
    return *(unsigned*)&p;
}

// fp16 weight tile (w error ~2^-12, within threshold budget)
__device__ __forceinline__ void load_w_h(const float* __restrict__ W,
                                         __half* Wd, int tid) {
#pragma unroll
    for (int i = 0; i < 4; i++) {
        int lin = tid + i * 256;          // 1024 float4 = 64 x 16
        int k = lin >> 4;
        int c4 = (lin & 15) << 2;
        float4 v = *(const float4*)(W + k * D + c4);
        __half2* pd = (__half2*)(Wd + k * WSTR + c4);
        pd[0] = __floats2half2_rn(v.x, v.y);
        pd[1] = __floats2half2_rn(v.z, v.w);
    }
}

// ---------------- K2/K3: tensor-core fused 2-layer MLP + BN stats ----------------
// A-fragments: layer 1 loaded directly from global fp32 (float2 per frag-half),
// layer 2 built in registers from relu(layer-1 accumulators). No X/H smem tiles.
__global__ __launch_bounds__(256, 2)
void k_mlp_tc(const float* __restrict__ Xext,
              const float* __restrict__ W1, const float* __restrict__ b1,
              const float* __restrict__ W2, const float* __restrict__ b2,
              int src_sel, int path, int nrows) {
    extern __shared__ char smem_raw[];
    __half* W1d = (__half*)smem_raw;
    __half* W2d = W1d + D * WSTR;
    float* sstat = (float*)(W2d + D * WSTR);   // [sum(64) | sumsq(64)]

    const float* X = (src_sel == 0) ? g_acc : Xext;
    __half* Y = (path == 0) ? g_hn : g_en;

    int tid = threadIdx.x;
    int warp = tid >> 5;
    int lane = tid & 31;
    int g = lane >> 2;
    int qp = lane & 3;
    int base = blockIdx.x * TROWS;

    if (tid < 2 * D) sstat[tid] = 0.f;
    load_w_h(W1, W1d, tid);
    load_w_h(W2, W2d, tid);
    __syncthreads();

    // per-lane B base: lanes 0-15 rows of first 8-col tile; 16-31 second tile
    const __half* wlane1 = W1d + (lane & 15) * WSTR + (lane >> 4) * 8;
    const __half* wlane2 = W2d + (lane & 15) * WSTR + (lane >> 4) * 8;

    // this thread's output rows (per mt): ra = rowg[mt], rb = ra + 8
    int rowg[2];
    rowg[0] = base + warp * 32 + g;
    rowg[1] = rowg[0] + 16;
    bool va[2], vb[2];
    va[0] = rowg[0] < nrows; vb[0] = rowg[0] + 8 < nrows;
    va[1] = rowg[1] < nrows; vb[1] = rowg[1] + 8 < nrows;

    // ---- layer 1: acc1 = X @ W1 + b1, A direct from global ----
    float acc1[2][8][4];
#pragma unroll
    for (int nt = 0; nt < 8; nt++) {
        float bv0 = __ldg(b1 + nt * 8 + 2 * qp);
        float bv1 = __ldg(b1 + nt * 8 + 2 * qp + 1);
#pragma unroll
        for (int mt = 0; mt < 2; mt++) {
            acc1[mt][nt][0] = bv0; acc1[mt][nt][1] = bv1;
            acc1[mt][nt][2] = bv0; acc1[mt][nt][3] = bv1;
        }
    }
#pragma unroll
    for (int kk = 0; kk < 4; kk++) {
        unsigned a[2][4];
#pragma unroll
        for (int mt = 0; mt < 2; mt++) {
            const float* p0 = X + (size_t)rowg[mt] * D + kk * 16 + 2 * qp;
            const float* p1 = p0 + 8 * D;     // row +8
            float2 z = make_float2(0.f, 0.f);
            float2 v00 = va[mt] ? *(const float2*)p0 : z;
            float2 v01 = va[mt] ? *(const float2*)(p0 + 8) : z;
            float2 v10 = vb[mt] ? *(const float2*)p1 : z;
            float2 v11 = vb[mt] ? *(const float2*)(p1 + 8) : z;
            a[mt][0] = packh2(v00.x, v00.y);
            a[mt][1] = packh2(v10.x, v10.y);
            a[mt][2] = packh2(v01.x, v01.y);
            a[mt][3] = packh2(v11.x, v11.y);
        }
#pragma unroll
        for (int nt2 = 0; nt2 < 4; nt2++) {
            unsigned b[4];
            ldmB4(b, wlane1 + kk * 16 * WSTR + nt2 * 16);
#pragma unroll
            for (int mt = 0; mt < 2; mt++) {
                mma_f16(acc1[mt][2 * nt2 + 0], a[mt], b + 0);
                mma_f16(acc1[mt][2 * nt2 + 1], a[mt], b + 2);
            }
        }
    }

    // ---- relu + repack acc1 into layer-2 A fragments (registers only) ----
    // C-tile nt of layer 1 covers layer-2 k-cols [8nt, 8nt+8): kk block uses nt=2kk,2kk+1
    unsigned aH[4][2][4];
#pragma unroll
    for (int kk = 0; kk < 4; kk++) {
#pragma unroll
        for (int mt = 0; mt < 2; mt++) {
            const float* c0 = acc1[mt][2 * kk];
            const float* c1 = acc1[mt][2 * kk + 1];
            aH[kk][mt][0] = packh2(fmaxf(c0[0], 0.f), fmaxf(c0[1], 0.f));
            aH[kk][mt][1] = packh2(fmaxf(c0[2], 0.f), fmaxf(c0[3], 0.f));
            aH[kk][mt][2] = packh2(fmaxf(c1[0], 0.f), fmaxf(c1[1], 0.f));
            aH[kk][mt][3] = packh2(fmaxf(c1[2], 0.f), fmaxf(c1[3], 0.f));
        }
    }

    // ---- layer 2 (nt2-outer, fused epilogue) ----
#pragma unroll
    for (int nt2 = 0; nt2 < 4; nt2++) {
        float acc2[2][2][4];
#pragma unroll
        for (int j = 0; j < 2; j++) {
            float bv0 = __ldg(b2 + (2 * nt2 + j) * 8 + 2 * qp);
            float bv1 = __ldg(b2 + (2 * nt2 + j) * 8 + 2 * qp + 1);
#pragma unroll
            for (int mt = 0; mt < 2; mt++) {
                acc2[mt][j][0] = bv0; acc2[mt][j][1] = bv1;
                acc2[mt][j][2] = bv0; acc2[mt][j][3] = bv1;
            }
        }
#pragma unroll
        for (int kk = 0; kk < 4; kk++) {
            unsigned b[4];
            ldmB4(b, wlane2 + kk * 16 * WSTR + nt2 * 16);
#pragma unroll
            for (int mt = 0; mt < 2; mt++) {
                mma_f16(acc2[mt][0], aH[kk][mt], b + 0);
                mma_f16(acc2[mt][1], aH[kk][mt], b + 2);
            }
        }
        // fused epilogue for the two 8-col tiles of this nt2
#pragma unroll
        for (int j = 0; j < 2; j++) {
            int col = (2 * nt2 + j) * 8 + 2 * qp;
#pragma unroll
            for (int mt = 0; mt < 2; mt++) {
                int ra = rowg[mt];
                int rb = ra + 8;
                float c0 = acc2[mt][j][0], c1 = acc2[mt][j][1];
                float c2 = acc2[mt][j][2], c3 = acc2[mt][j][3];
                if (va[mt]) *(__half2*)(Y + (size_t)ra * D + col) = __floats2half2_rn(c0, c1);
                if (vb[mt]) *(__half2*)(Y + (size_t)rb * D + col) = __floats2half2_rn(c2, c3);
                float s0 = (va[mt] ? c0 : 0.f) + (vb[mt] ? c2 : 0.f);
                float s1 = (va[mt] ? c1 : 0.f) + (vb[mt] ? c3 : 0.f);
                float q0 = (va[mt] ? c0 * c0 : 0.f) + (vb[mt] ? c2 * c2 : 0.f);
                float q1 = (va[mt] ? c1 * c1 : 0.f) + (vb[mt] ? c3 * c3 : 0.f);
#pragma unroll
                for (int off = 4; off < 32; off <<= 1) {
                    s0 += __shfl_xor_sync(0xffffffffu, s0, off);
                    s1 += __shfl_xor_sync(0xffffffffu, s1, off);
                    q0 += __shfl_xor_sync(0xffffffffu, q0, off);
                    q1 += __shfl_xor_sync(0xffffffffu, q1, off);
                }
                if (lane < 4) {           // lane == qp group representative
                    atomicAdd(sstat + col, s0);
                    atomicAdd(sstat + col + 1, s1);
                    atomicAdd(sstat + 64 + col, q0);
                    atomicAdd(sstat + 64 + col + 1, q1);
                }
            }
        }
    }
    __syncthreads();
    if (tid < D) {
        int slot = blockIdx.x & (NSLOT - 1);
        float* p = g_partial + ((path * NSLOT + slot) * 2) * D;
        atomicAdd(p + tid, sstat[tid]);
        atomicAdd(p + D + tid, sstat[64 + tid]);
    }
}

// ---------------- K4: finalize BN -> per-column scale/shift ----------------
__global__ void k_finalize(const float* __restrict__ gamma_h, const float* __restrict__ beta_h,
                           const float* __restrict__ gamma_e, const float* __restrict__ beta_e,
                           int n_nodes, int n_edges) {
    int t = threadIdx.x;            // 128 threads
    int path = t >> 6;
    int col = t & 63;
    float n = (path == 0) ? (float)n_nodes : (float)n_edges;
    float s = 0.f, q = 0.f;
    for (int slot = 0; slot < NSLOT; slot++) {
        const float* p = g_partial + ((path * NSLOT + slot) * 2) * D;
        s += p[col];
        q += p[D + col];
    }
    float mean = s / n;
    float var = q / n - mean * mean;
    float rstd = rsqrtf(var + BN_EPS);
    float gamma = (path == 0) ? __ldg(gamma_h + col) : __ldg(gamma_e + col);
    float beta  = (path == 0) ? __ldg(beta_h + col)  : __ldg(beta_e + col);
    float scale = gamma * rstd;
    float shift = beta - mean * scale;
    g_final[path * 2 * D + col] = scale;
    g_final[path * 2 * D + D + col] = shift;
}

// ---------------- K5/K6: epilogue  out = in + relu(scale*y + shift) ----------------
__global__ void k_epi(const float* __restrict__ inp, int path,
                      float* __restrict__ out, int nrows) {
    int i = blockIdx.x * blockDim.x + threadIdx.x;
    int total4 = nrows * (D / 4);
    if (i >= total4) return;
    const __half* y = (path == 0) ? g_hn : g_en;
    int c4 = (i & 15) * 4;
    const float* sc = g_final + path * 2 * D;
    const float* sh = sc + D;
    const __half2* yp = (const __half2*)(y + (((size_t)i >> 4) << 6) + c4);
    float2 y01 = __half22float2(yp[0]);
    float2 y23 = __half22float2(yp[1]);
    float4 xv = *((const float4*)inp + i);
    float4 o;
    o.x = xv.x + fmaxf(fmaf(sc[c4 + 0], y01.x, sh[c4 + 0]), 0.f);
    o.y = xv.y + fmaxf(fmaf(sc[c4 + 1], y01.y, sh[c4 + 1]), 0.f);
    o.z = xv.z + fmaxf(fmaf(sc[c4 + 2], y23.x, sh[c4 + 2]), 0.f);
    o.w = xv.w + fmaxf(fmaf(sc[c4 + 3], y23.y, sh[c4 + 3]), 0.f);
    *((float4*)out + i) = o;
}

// ---------------- launch ----------------
static cudaStream_t g_s2 = nullptr;
static cudaEvent_t g_ev0, g_ev1, g_ev2, g_ev3;

extern "C" void kernel_launch(void* const* d_in, const int* in_sizes, int n_in,
                              void* d_out, int out_size) {
    if (g_s2 == nullptr) {   // one-time resource creation (host-side, not captured work)
        cudaStreamCreateWithFlags(&g_s2, cudaStreamNonBlocking);
        cudaEventCreateWithFlags(&g_ev0, cudaEventDisableTiming);
        cudaEventCreateWithFlags(&g_ev1, cudaEventDisableTiming);
        cudaEventCreateWithFlags(&g_ev2, cudaEventDisableTiming);
        cudaEventCreateWithFlags(&g_ev3, cudaEventDisableTiming);
    }

    const float* h   = (const float*)d_in[0];
    const float* e   = (const float*)d_in[1];
    const int*   src = (const int*)d_in[2];
    const int*   dst = (const int*)d_in[3];
    const float* eps = (const float*)d_in[4];
    const float* W1  = (const float*)d_in[5];
    const float* b1  = (const float*)d_in[6];
    const float* W2  = (const float*)d_in[7];
    const float* b2  = (const float*)d_in[8];
    const float* gh  = (const float*)d_in[9];
    const float* bh  = (const float*)d_in[10];
    const float* ge  = (const float*)d_in[11];
    const float* be  = (const float*)d_in[12];

    int n_nodes = in_sizes[0] / D;
    int n_edges = in_sizes[1] / D;
    float* out = (float*)d_out;
    float* out_h = out;
    float* out_e = out + (size_t)n_nodes * D;

    int t4n = n_nodes * (D / 4);
    int t4e = n_edges * (D / 4);

    // 2 fp16 weight tiles + stats only
    const int SMEM_BYTES = (2 * D * WSTR) * 2 + 2 * D * 4;  // 18944
    cudaFuncSetAttribute(k_mlp_tc, cudaFuncAttributeMaxDynamicSharedMemorySize, SMEM_BYTES);

    // ---- fork: edge chain (zero edge partials -> edge MLP) on side stream ----
    cudaEventRecord(g_ev0, 0);
    cudaStreamWaitEvent(g_s2, g_ev0, 0);
    k_zero_e<<<(NSLOT * 2 * D + 255) / 256, 256, 0, g_s2>>>();
    k_mlp_tc<<<(n_edges + TROWS - 1) / TROWS, 256, SMEM_BYTES, g_s2>>>(
        e, W1, b1, W2, b2, /*src_sel=*/1, /*path=*/1, n_edges);

    // ---- main stream: node chain (init zeroes node partials only) ----
    k_init<<<(t4n + 255) / 256, 256>>>(h, eps, n_nodes);
    {
        long long threads = (long long)n_edges * 16;
        int blocks = (int)((threads + 255) / 256);
        k_scatter<<<blocks, 256>>>(h, src, dst, n_edges);
    }
    k_mlp_tc<<<(n_nodes + TROWS - 1) / TROWS, 256, SMEM_BYTES>>>(
        nullptr, W1, b1, W2, b2, /*src_sel=*/0, /*path=*/0, n_nodes);

    // ---- join: both stat sets complete before finalize ----
    cudaEventRecord(g_ev1, g_s2);
    cudaStreamWaitEvent(0, g_ev1, 0);
    k_finalize<<<1, 128>>>(gh, bh, ge, be, n_nodes, n_edges);

    // ---- fork epilogues: node epi on side stream, edge epi on main ----
    cudaEventRecord(g_ev2, 0);
    cudaStreamWaitEvent(g_s2, g_ev2, 0);
    k_epi<<<(t4n + 255) / 256, 256, 0, g_s2>>>(h, /*path=*/0, out_h, n_nodes);
    k_epi<<<(t4e + 255) / 256, 256>>>(e, /*path=*/1, out_e, n_edges);
    cudaEventRecord(g_ev3, g_s2);
    cudaStreamWaitEvent(0, g_ev3, 0);
}